// round 9
// baseline (speedup 1.0000x reference)
#include <cuda_runtime.h>
#include <math.h>

#define BB 4
#define SS 2048
#define HH 1024
#define NHEAD 16
#define HDIM 64
#define MM (BB * SS)   // 8192
#define NQKV 1152      // 1024 (Q) + 64 (K) + 64 (V)

// ---------------------------------------------------------------------------
// scratch (__device__ globals; allocation-free)
// ---------------------------------------------------------------------------
__device__ unsigned g_xp[MM * HH];         // X, tf32, pair-interleaved cols
__device__ unsigned g_wqkv[HH * NQKV];     // Wq|Wk|Wv packed, kperm layout
__device__ unsigned g_wo[HH * HH];         // Wo, kperm layout
__device__ unsigned g_q [MM * HH];         // Q, tf32, 0.125*log2e, head-block pair-interleaved
__device__ unsigned g_k [MM * HDIM];       // K, tf32, pair-interleaved cols
__device__ unsigned g_v [MM * HDIM];       // V, tf32, [s/8][d][8] layout
__device__ unsigned g_at[MM * HH];         // attn out, tf32, pair-interleaved

// ---------------------------------------------------------------------------
// helpers
// ---------------------------------------------------------------------------
__device__ __forceinline__ unsigned f2tf(float f) {
    unsigned u;
    asm("cvt.rna.tf32.f32 %0, %1;" : "=r"(u) : "f"(f));
    return u;
}
__device__ __forceinline__ float ex2(float f) {
    float r;
    asm("ex2.approx.f32 %0, %1;" : "=f"(r) : "f"(f));
    return r;
}
__device__ __forceinline__ int perm8(int c) {
    return (c & ~7) | ((c & 3) << 1) | ((c >> 2) & 1);
}
__device__ __forceinline__ size_t kperm(int k, int n, int N) {
    return (size_t)(k >> 3) * N * 8 + n * 8 + (k & 3) * 2 + ((k >> 2) & 1);
}
__device__ __forceinline__ void mma_tf32(float c[4],
                                         unsigned a0, unsigned a1,
                                         unsigned a2, unsigned a3,
                                         unsigned b0, unsigned b1) {
    asm volatile(
        "mma.sync.aligned.m16n8k8.row.col.f32.tf32.tf32.f32 "
        "{%0,%1,%2,%3}, {%4,%5,%6,%7}, {%8,%9}, {%0,%1,%2,%3};"
        : "+f"(c[0]), "+f"(c[1]), "+f"(c[2]), "+f"(c[3])
        : "r"(a0), "r"(a1), "r"(a2), "r"(a3), "r"(b0), "r"(b1));
}
__device__ __forceinline__ void cpa16(unsigned* smem_dst, const unsigned* gmem_src) {
    unsigned s = (unsigned)__cvta_generic_to_shared(smem_dst);
    asm volatile("cp.async.cg.shared.global [%0], [%1], 16;" :: "r"(s), "l"(gmem_src));
}
// volatile 64-bit global load: prevents CSE/hoisting (register-pressure control)
__device__ __forceinline__ uint2 ldg64v(const unsigned* p) {
    uint2 r;
    asm volatile("ld.global.nc.v2.u32 {%0,%1}, [%2];" : "=r"(r.x), "=r"(r.y) : "l"(p));
    return r;
}
#define CP_COMMIT() asm volatile("cp.async.commit_group;")
#define CP_WAIT0()  asm volatile("cp.async.wait_group 0;")

// ---------------------------------------------------------------------------
// pre-convert kernels (2 launches)
// ---------------------------------------------------------------------------
__global__ void cvt_x_sh(const float4* __restrict__ in, uint4* __restrict__ out, int n4) {
    int idx = blockIdx.x * 256 + threadIdx.x;
    if (idx < n4) {
        float4 v = in[idx];
        unsigned x0 = f2tf(v.x), x1 = f2tf(v.y), x2 = f2tf(v.z), x3 = f2tf(v.w);
        bool odd = threadIdx.x & 1;
        unsigned a = odd ? x0 : x2;
        unsigned b = odd ? x1 : x3;
        unsigned sa = __shfl_xor_sync(0xffffffffu, a, 1);
        unsigned sb = __shfl_xor_sync(0xffffffffu, b, 1);
        uint4 o;
        if (!odd) { o.x = x0; o.y = sa; o.z = x1; o.w = sb; }
        else      { o.x = sa; o.y = x2; o.z = sb; o.w = x3; }
        out[idx] = o;
    }
}
__global__ void cvt_w_all(const float* __restrict__ Wq, const float* __restrict__ Wk,
                          const float* __restrict__ Wv, const float* __restrict__ Wo,
                          unsigned* __restrict__ wqkv, unsigned* __restrict__ wo)
{
    int i = blockIdx.x * 256 + threadIdx.x;
    if (i < HH * HH) {
        int nn = i & (HH - 1), k = i >> 10;
        wqkv[kperm(k, nn, NQKV)] = f2tf(Wq[i]);
    } else if (i < HH * HH + HH * 128) {
        int j = i - HH * HH;
        int nn = j & 127, k = j >> 7;
        float v = (nn < HDIM) ? Wk[k * HDIM + nn] : Wv[k * HDIM + nn - HDIM];
        wqkv[kperm(k, HH + nn, NQKV)] = f2tf(v);
    } else if (i < 2 * HH * HH + HH * 128) {
        int j = i - HH * HH - HH * 128;
        int nn = j & (HH - 1), k = j >> 10;
        wo[kperm(k, nn, HH)] = f2tf(Wo[j]);
    }
}

// ---------------------------------------------------------------------------
// double-buffered tf32 GEMM. A: pair-interleaved cols [M][K]. W: kperm.
// MODE 0: fp32+bias -> final out. MODE 5: QKV routing epilogue
// (Q now stored pair-interleaved WITHIN each head's 64-dim block).
// BM=256, BN=128, BK=32, 256 threads, 8 warps (4m x 2n), warp tile 64x64.
// ---------------------------------------------------------------------------
template <int MODE>
__global__ __launch_bounds__(256) void gemm_db(
    const unsigned* __restrict__ A, const unsigned* __restrict__ W,
    const float* __restrict__ bias, const float* __restrict__ bias2,
    const float* __restrict__ bias3,
    void* __restrict__ Cout, void* __restrict__ Cout2, void* __restrict__ Cout3,
    int M, int N, int K, float oscale)
{
    constexpr int BM = 256, BN = 128, BK = 32;
    constexpr int NTHR = 256;
    constexpr int AST = 40;
    constexpr int BWORDS = 4 * BN * 8;

    extern __shared__ unsigned sm[];
    unsigned* As = sm;
    unsigned* Bs = sm + 2 * BM * AST;

    const int tid = threadIdx.x;
    const int wid = tid >> 5, lane = tid & 31, g = lane >> 2, tg = lane & 3;
    const int wm = (wid >> 1) * 64;
    const int wn = (wid & 1) * 64;
    const int rowBase = blockIdx.y * BM, colBase = blockIdx.x * BN;

    float acc[4][8][4];
#pragma unroll
    for (int mi = 0; mi < 4; mi++)
#pragma unroll
        for (int nj = 0; nj < 8; nj++)
#pragma unroll
            for (int r = 0; r < 4; r++) acc[mi][nj][r] = 0.0f;

    auto issue = [&](int kt, int buf) {
        const unsigned* Ag = A + (size_t)rowBase * K + kt;
        unsigned* Ab = As + buf * BM * AST;
#pragma unroll
        for (int i = 0; i < (BM * BK / 4) / NTHR; i++) {
            int ch = tid + i * NTHR;
            int r = ch >> 3, cw = ch & 7;
            cpa16(Ab + r * AST + cw * 4, Ag + (size_t)r * K + cw * 4);
        }
        const unsigned* Wg = W + (size_t)(kt >> 3) * N * 8 + (size_t)colBase * 8;
        unsigned* Bb = Bs + buf * BWORDS;
#pragma unroll
        for (int i = 0; i < (BWORDS / 4) / NTHR; i++) {
            int ch = tid + i * NTHR;
            int r = ch / (BN * 2), cw = ch % (BN * 2);
            cpa16(Bb + r * BN * 8 + cw * 4, Wg + (size_t)r * N * 8 + cw * 4);
        }
    };

    issue(0, 0);
    CP_COMMIT();

    const int T = K / BK;
    for (int t = 0; t < T; t++) {
        CP_WAIT0();
        __syncthreads();
        if (t + 1 < T) {
            issue((t + 1) * BK, (t + 1) & 1);
            CP_COMMIT();
        }

        const unsigned* Ab = As + (t & 1) * BM * AST;
        const unsigned* Bb = Bs + (t & 1) * BWORDS;
#pragma unroll
        for (int ks = 0; ks < 4; ks++) {
            unsigned a[4][4];
#pragma unroll
            for (int mi = 0; mi < 4; mi++) {
                int row = wm + mi * 16 + g;
                uint2 lo = *(const uint2*)(Ab + row * AST + ks * 8 + tg * 2);
                uint2 hi = *(const uint2*)(Ab + (row + 8) * AST + ks * 8 + tg * 2);
                a[mi][0] = lo.x; a[mi][2] = lo.y;
                a[mi][1] = hi.x; a[mi][3] = hi.y;
            }
#pragma unroll
            for (int nj = 0; nj < 8; nj++) {
                uint2 bb = *(const uint2*)(Bb + ks * BN * 8 + (wn + nj * 8 + g) * 8 + tg * 2);
#pragma unroll
                for (int mi = 0; mi < 4; mi++)
                    mma_tf32(acc[mi][nj], a[mi][0], a[mi][1], a[mi][2], a[mi][3], bb.x, bb.y);
            }
        }
    }

#pragma unroll
    for (int nj = 0; nj < 8; nj++) {
        int col = colBase + wn + nj * 8 + 2 * tg;
        float bx, by;
        if (MODE == 5) {
            if (col < HH)            { bx = bias[col];        by = bias[col + 1]; }
            else if (col < HH + 64)  { bx = bias2[col - HH];  by = bias2[col - HH + 1]; }
            else                     { bx = bias3[col - HH - 64]; by = bias3[col - HH - 63]; }
        } else {
            bx = bias[col]; by = bias[col + 1];
        }
#pragma unroll
        for (int mi = 0; mi < 4; mi++) {
            int row = rowBase + wm + mi * 16 + g;
            float v00 = acc[mi][nj][0] + bx, v01 = acc[mi][nj][1] + by;
            float v10 = acc[mi][nj][2] + bx, v11 = acc[mi][nj][3] + by;
            if (MODE == 0) {
                float* o = (float*)Cout;
                *(float2*)(o + (size_t)row * N + col) = make_float2(v00, v01);
                *(float2*)(o + (size_t)(row + 8) * N + col) = make_float2(v10, v11);
            } else {
                if (col < HH) {
                    // Q: pair-interleave within the head's 64-dim block
                    unsigned* o = (unsigned*)Cout;
                    int hb = col & ~63;
                    int d  = col & 63;
                    int p0 = hb + perm8(d), p1 = hb + perm8(d + 1);
                    o[(size_t)row * HH + p0]       = f2tf(v00 * oscale);
                    o[(size_t)row * HH + p1]       = f2tf(v01 * oscale);
                    o[(size_t)(row + 8) * HH + p0] = f2tf(v10 * oscale);
                    o[(size_t)(row + 8) * HH + p1] = f2tf(v11 * oscale);
                } else if (col < HH + 64) {
                    unsigned* o = (unsigned*)Cout2;
                    int d = col - HH;
                    o[(size_t)row * HDIM + perm8(d)]           = f2tf(v00);
                    o[(size_t)row * HDIM + perm8(d + 1)]       = f2tf(v01);
                    o[(size_t)(row + 8) * HDIM + perm8(d)]     = f2tf(v10);
                    o[(size_t)(row + 8) * HDIM + perm8(d + 1)] = f2tf(v11);
                } else {
                    unsigned* o = (unsigned*)Cout3;
                    int d = col - HH - 64;
                    o[kperm(row, d, HDIM)]         = f2tf(v00);
                    o[kperm(row, d + 1, HDIM)]     = f2tf(v01);
                    o[kperm(row + 8, d, HDIM)]     = f2tf(v10);
                    o[kperm(row + 8, d + 1, HDIM)] = f2tf(v11);
                }
            }
        }
    }
}

// ---------------------------------------------------------------------------
// MQA flash attention v7: 2 m-frags/warp (each K/V B-frag LDS serves 2 MMAs),
// Q A-frags re-loaded per key-tile via volatile LDG.64 (L1-hit; keeps regs
// under the 128 cap for 2 CTAs/SM). q-tile 256 (8 warps x 32 rows),
// key tile 64 in two 32-key halves. grid = (S/256, NH, B).
// ---------------------------------------------------------------------------
__global__ __launch_bounds__(256, 2) void mqa_attn_tc7(
    const unsigned* __restrict__ qp, const unsigned* __restrict__ kp,
    const unsigned* __restrict__ vp, unsigned* __restrict__ outp)
{
    extern __shared__ unsigned sm[];
    unsigned* Ks = sm;                    // [2][64][72]
    unsigned* Vs = sm + 2 * 64 * 72;      // [2][4096]
    unsigned* Ps = Vs + 2 * 4096;         // [8][32][36]

    const int b = blockIdx.z, h = blockIdx.y;
    const int qBase = blockIdx.x * 256;
    const int tid = threadIdx.x, wid = tid >> 5, lane = tid & 31;
    const int g = lane >> 2, tg = lane & 3;

    // Q row base pointers for the two m-frags (rows g; +8*HH gives row g+8)
    const unsigned* qr0;
    const unsigned* qr1;
    {
        int row0 = qBase + wid * 32 + g;
        qr0 = qp + (size_t)(b * SS + row0) * HH + h * HDIM + tg * 2;
        qr1 = qr0 + (size_t)16 * HH;
    }

    float o[2][8][4];
#pragma unroll
    for (int mi = 0; mi < 2; mi++)
#pragma unroll
        for (int nj = 0; nj < 8; nj++)
#pragma unroll
            for (int r = 0; r < 4; r++) o[mi][nj][r] = 0.0f;
    float lp[4] = {0.0f, 0.0f, 0.0f, 0.0f};

    auto issue = [&](int t, int buf) {
        const unsigned* kg = kp + (size_t)(b * SS + t * 64) * HDIM;
        unsigned* kb = Ks + buf * 64 * 72;
#pragma unroll
        for (int i = 0; i < 4; i++) {
            int ch = tid + i * 256;
            int r = ch >> 4, cw = ch & 15;
            cpa16(kb + r * 72 + cw * 4, kg + r * 64 + cw * 4);
        }
        const unsigned* vg = vp + (size_t)(b * SS + t * 64) * HDIM;
        unsigned* vb = Vs + buf * 4096;
#pragma unroll
        for (int i = 0; i < 4; i++) {
            int ch = tid + i * 256;
            cpa16(vb + ch * 4, vg + ch * 4);
        }
    };

    issue(0, 0);
    CP_COMMIT();

    unsigned* Pw = Ps + wid * 32 * 36;
    const int T = SS / 64;
    for (int t = 0; t < T; t++) {
        CP_WAIT0();
        __syncthreads();
        if (t + 1 < T) {
            issue(t + 1, (t + 1) & 1);
            CP_COMMIT();
        }

        const unsigned* Kb = Ks + (t & 1) * 64 * 72;
        const unsigned* Vb = Vs + (t & 1) * 4096;

#pragma unroll
        for (int hf = 0; hf < 2; hf++) {
            // S = Q K^T  (32 q x 32 keys per warp; Q frags streamed from L1)
            float s[2][4][4];
#pragma unroll
            for (int mi = 0; mi < 2; mi++)
#pragma unroll
                for (int nj = 0; nj < 4; nj++)
#pragma unroll
                    for (int r = 0; r < 4; r++) s[mi][nj][r] = 0.0f;
#pragma unroll
            for (int kf = 0; kf < 8; kf++) {
                uint2 q0g = ldg64v(qr0 + kf * 8);
                uint2 q0h = ldg64v(qr0 + (size_t)8 * HH + kf * 8);
                uint2 q1g = ldg64v(qr1 + kf * 8);
                uint2 q1h = ldg64v(qr1 + (size_t)8 * HH + kf * 8);
#pragma unroll
                for (int nj = 0; nj < 4; nj++) {
                    uint2 bb = *(const uint2*)(Kb + (hf * 32 + nj * 8 + g) * 72 + kf * 8 + tg * 2);
                    mma_tf32(s[0][nj], q0g.x, q0h.x, q0g.y, q0h.y, bb.x, bb.y);
                    mma_tf32(s[1][nj], q1g.x, q1h.x, q1g.y, q1h.y, bb.x, bb.y);
                }
            }

            // P = 2^S -> smem, accumulate row sums
#pragma unroll
            for (int mi = 0; mi < 2; mi++)
#pragma unroll
                for (int nj = 0; nj < 4; nj++) {
                    float p0 = ex2(s[mi][nj][0]);
                    float p1 = ex2(s[mi][nj][1]);
                    float p2 = ex2(s[mi][nj][2]);
                    float p3 = ex2(s[mi][nj][3]);
                    lp[mi * 2 + 0] += p0 + p1;
                    lp[mi * 2 + 1] += p2 + p3;
                    int col = nj * 8 + 2 * tg;
                    *(uint2*)(Pw + (mi * 16 + g) * 36 + col)     = make_uint2(f2tf(p0), f2tf(p1));
                    *(uint2*)(Pw + (mi * 16 + g + 8) * 36 + col) = make_uint2(f2tf(p2), f2tf(p3));
                }
            __syncwarp();

            // O += P V  (V B-frags shared across both m-frags)
            unsigned pa[2][4][4];
#pragma unroll
            for (int mi = 0; mi < 2; mi++)
#pragma unroll
                for (int kf = 0; kf < 4; kf++) {
                    int col = kf * 8 + tg;
                    pa[mi][kf][0] = Pw[(mi * 16 + g) * 36 + col];
                    pa[mi][kf][1] = Pw[(mi * 16 + g + 8) * 36 + col];
                    pa[mi][kf][2] = Pw[(mi * 16 + g) * 36 + col + 4];
                    pa[mi][kf][3] = Pw[(mi * 16 + g + 8) * 36 + col + 4];
                }
#pragma unroll
            for (int nj = 0; nj < 8; nj++) {
#pragma unroll
                for (int kf = 0; kf < 4; kf++) {
                    uint2 bb = *(const uint2*)(Vb + (hf * 4 + kf) * 512 + (nj * 8 + g) * 8 + tg * 2);
                    mma_tf32(o[0][nj], pa[0][kf][0], pa[0][kf][1], pa[0][kf][2], pa[0][kf][3], bb.x, bb.y);
                    mma_tf32(o[1][nj], pa[1][kf][0], pa[1][kf][1], pa[1][kf][2], pa[1][kf][3], bb.x, bb.y);
                }
            }
            __syncwarp();
        }
    }

    // reduce row sums across quad, normalize, store pair-interleaved
#pragma unroll
    for (int r = 0; r < 4; r++) {
        lp[r] += __shfl_xor_sync(0xffffffffu, lp[r], 1);
        lp[r] += __shfl_xor_sync(0xffffffffu, lp[r], 2);
        lp[r] = 1.0f / lp[r];
    }
#pragma unroll
    for (int mi = 0; mi < 2; mi++) {
        int row = qBase + wid * 32 + mi * 16 + g;
        size_t base = (size_t)(b * SS + row) * HH;
#pragma unroll
        for (int nj = 0; nj < 8; nj++) {
            int cg = h * HDIM + nj * 8 + 2 * tg;
            outp[base + perm8(cg)]                      = f2tf(o[mi][nj][0] * lp[mi * 2]);
            outp[base + perm8(cg + 1)]                  = f2tf(o[mi][nj][1] * lp[mi * 2]);
            outp[base + (size_t)8 * HH + perm8(cg)]     = f2tf(o[mi][nj][2] * lp[mi * 2 + 1]);
            outp[base + (size_t)8 * HH + perm8(cg + 1)] = f2tf(o[mi][nj][3] * lp[mi * 2 + 1]);
        }
    }
}

// ---------------------------------------------------------------------------
extern "C" void kernel_launch(void* const* d_in, const int* in_sizes, int n_in,
                              void* d_out, int out_size)
{
    const float* X  = (const float*)d_in[0];
    const float* Wq = (const float*)d_in[1];
    const float* bq = (const float*)d_in[2];
    const float* Wk = (const float*)d_in[3];
    const float* bk = (const float*)d_in[4];
    const float* Wv = (const float*)d_in[5];
    const float* bv = (const float*)d_in[6];
    const float* Wo = (const float*)d_in[7];
    const float* bo = (const float*)d_in[8];
    float* out = (float*)d_out;

    unsigned *xp, *wqkv, *wo, *q, *k, *v, *at;
    cudaGetSymbolAddress((void**)&xp,   g_xp);
    cudaGetSymbolAddress((void**)&wqkv, g_wqkv);
    cudaGetSymbolAddress((void**)&wo,   g_wo);
    cudaGetSymbolAddress((void**)&q,    g_q);
    cudaGetSymbolAddress((void**)&k,    g_k);
    cudaGetSymbolAddress((void**)&v,    g_v);
    cudaGetSymbolAddress((void**)&at,   g_at);

    const int smA  = (2 * 256 * 40 + 2 * 4 * 128 * 8) * 4;          // 114688
    const int smAt = (2 * 64 * 72 + 2 * 4096 + 8 * 32 * 36) * 4;    // 106496

    cudaFuncSetAttribute(gemm_db<0>, cudaFuncAttributeMaxDynamicSharedMemorySize, smA);
    cudaFuncSetAttribute(gemm_db<5>, cudaFuncAttributeMaxDynamicSharedMemorySize, smA);
    cudaFuncSetAttribute(mqa_attn_tc7, cudaFuncAttributeMaxDynamicSharedMemorySize, smAt);
    cudaFuncSetAttribute(mqa_attn_tc7, cudaFuncAttributePreferredSharedMemoryCarveout, 100);

    const float qscale = 0.125f * 1.44269504088896340736f;  // 1/sqrt(64) * log2(e)

    // launch 1: X convert
    cvt_x_sh<<<(MM * HH / 4 + 255) / 256, 256>>>((const float4*)X, (uint4*)xp, MM * HH / 4);
    // launch 2: all weight converts
    const int nw = 2 * HH * HH + HH * 128;
    cvt_w_all<<<(nw + 255) / 256, 256>>>(Wq, Wk, Wv, Wo, wqkv, wo);
    // launch 3: fused QKV projection
    gemm_db<5><<<dim3(NQKV / 128, MM / 256), 256, smA>>>(
        xp, wqkv, bq, bk, bv, q, k, v, MM, NQKV, HH, qscale);
    // launch 4 (ncu window): attention
    mqa_attn_tc7<<<dim3(SS / 256, NHEAD, BB), 256, smAt>>>(q, k, v, at);
    // launch 5: output projection
    gemm_db<0><<<dim3(HH / 128, MM / 256), 256, smA>>>(
        at, wo, bo, nullptr, nullptr, out, nullptr, nullptr, MM, HH, HH, 1.0f);
}

// round 10
// speedup vs baseline: 1.4974x; 1.4974x over previous
#include <cuda_runtime.h>
#include <math.h>

#define BB 4
#define SS 2048
#define HH 1024
#define NHEAD 16
#define HDIM 64
#define MM (BB * SS)   // 8192
#define NQKV 1152      // 1024 (Q) + 64 (K) + 64 (V)

// ---------------------------------------------------------------------------
// scratch (__device__ globals; allocation-free)
// ---------------------------------------------------------------------------
__device__ unsigned g_xp[MM * HH];         // X, tf32, pair-interleaved cols
__device__ unsigned g_wqkv[HH * NQKV];     // Wq|Wk|Wv packed, kperm layout
__device__ unsigned g_wo[HH * HH];         // Wo, kperm layout
__device__ unsigned g_q [MM * HH];         // Q, tf32, pre-scaled 0.125*log2e
__device__ unsigned g_k [MM * HDIM];       // K, tf32, pair-interleaved cols
__device__ unsigned g_v [MM * HDIM];       // V, tf32, [s/8][d][8] layout
__device__ unsigned g_at[MM * HH];         // attn out, tf32, pair-interleaved

// ---------------------------------------------------------------------------
// helpers
// ---------------------------------------------------------------------------
__device__ __forceinline__ unsigned f2tf(float f) {
    unsigned u;
    asm("cvt.rna.tf32.f32 %0, %1;" : "=r"(u) : "f"(f));
    return u;
}
__device__ __forceinline__ float ex2(float f) {
    float r;
    asm("ex2.approx.f32 %0, %1;" : "=f"(r) : "f"(f));
    return r;
}
__device__ __forceinline__ int perm8(int c) {
    return (c & ~7) | ((c & 3) << 1) | ((c >> 2) & 1);
}
__device__ __forceinline__ size_t kperm(int k, int n, int N) {
    return (size_t)(k >> 3) * N * 8 + n * 8 + (k & 3) * 2 + ((k >> 2) & 1);
}
__device__ __forceinline__ void mma_tf32(float c[4],
                                         unsigned a0, unsigned a1,
                                         unsigned a2, unsigned a3,
                                         unsigned b0, unsigned b1) {
    asm volatile(
        "mma.sync.aligned.m16n8k8.row.col.f32.tf32.tf32.f32 "
        "{%0,%1,%2,%3}, {%4,%5,%6,%7}, {%8,%9}, {%0,%1,%2,%3};"
        : "+f"(c[0]), "+f"(c[1]), "+f"(c[2]), "+f"(c[3])
        : "r"(a0), "r"(a1), "r"(a2), "r"(a3), "r"(b0), "r"(b1));
}
__device__ __forceinline__ void cpa16(unsigned* smem_dst, const unsigned* gmem_src) {
    unsigned s = (unsigned)__cvta_generic_to_shared(smem_dst);
    asm volatile("cp.async.cg.shared.global [%0], [%1], 16;" :: "r"(s), "l"(gmem_src));
}
#define CP_COMMIT() asm volatile("cp.async.commit_group;")
#define CP_WAIT0()  asm volatile("cp.async.wait_group 0;")

// ---------------------------------------------------------------------------
// pre-convert kernels (2 launches)
// ---------------------------------------------------------------------------
__global__ void cvt_x_sh(const float4* __restrict__ in, uint4* __restrict__ out, int n4) {
    int idx = blockIdx.x * 256 + threadIdx.x;
    if (idx < n4) {
        float4 v = in[idx];
        unsigned x0 = f2tf(v.x), x1 = f2tf(v.y), x2 = f2tf(v.z), x3 = f2tf(v.w);
        bool odd = threadIdx.x & 1;
        unsigned a = odd ? x0 : x2;
        unsigned b = odd ? x1 : x3;
        unsigned sa = __shfl_xor_sync(0xffffffffu, a, 1);
        unsigned sb = __shfl_xor_sync(0xffffffffu, b, 1);
        uint4 o;
        if (!odd) { o.x = x0; o.y = sa; o.z = x1; o.w = sb; }
        else      { o.x = sa; o.y = x2; o.z = sb; o.w = x3; }
        out[idx] = o;
    }
}
__global__ void cvt_w_all(const float* __restrict__ Wq, const float* __restrict__ Wk,
                          const float* __restrict__ Wv, const float* __restrict__ Wo,
                          unsigned* __restrict__ wqkv, unsigned* __restrict__ wo)
{
    int i = blockIdx.x * 256 + threadIdx.x;
    if (i < HH * HH) {
        int nn = i & (HH - 1), k = i >> 10;
        wqkv[kperm(k, nn, NQKV)] = f2tf(Wq[i]);
    } else if (i < HH * HH + HH * 128) {
        int j = i - HH * HH;
        int nn = j & 127, k = j >> 7;
        float v = (nn < HDIM) ? Wk[k * HDIM + nn] : Wv[k * HDIM + nn - HDIM];
        wqkv[kperm(k, HH + nn, NQKV)] = f2tf(v);
    } else if (i < 2 * HH * HH + HH * 128) {
        int j = i - HH * HH - HH * 128;
        int nn = j & (HH - 1), k = j >> 10;
        wo[kperm(k, nn, HH)] = f2tf(Wo[j]);
    }
}

// ---------------------------------------------------------------------------
// double-buffered tf32 GEMM v2: 2 CTAs/SM.
// A: pair-interleaved cols [M][K] in gmem -> smem [4][128][8] kperm (pad-free).
// W: kperm [K/8][N][8] -> smem [4][128][8].
// BM=128, BN=128, BK=32, 256 threads, 8 warps (2m x 4n), warp tile 64x32.
// acc = 64 regs -> ~105 total, 2 CTAs co-resident (smem 64KB/CTA).
// MODE 0: fp32+bias -> final out. MODE 5: QKV routing epilogue.
// ---------------------------------------------------------------------------
template <int MODE>
__global__ __launch_bounds__(256, 2) void gemm_db(
    const unsigned* __restrict__ A, const unsigned* __restrict__ W,
    const float* __restrict__ bias, const float* __restrict__ bias2,
    const float* __restrict__ bias3,
    void* __restrict__ Cout, void* __restrict__ Cout2, void* __restrict__ Cout3,
    int M, int N, int K, float oscale)
{
    constexpr int BM = 128, BN = 128, BK = 32;
    constexpr int STAGE = 4 * BM * 8;      // 4096 words per stage

    extern __shared__ unsigned sm[];
    unsigned* As = sm;                     // [2][4][128][8]
    unsigned* Bs = sm + 2 * STAGE;         // [2][4][128][8]

    const int tid = threadIdx.x;
    const int wid = tid >> 5, lane = tid & 31, g = lane >> 2, tg = lane & 3;
    const int wm = (wid & 1) * 64;
    const int wn = (wid >> 1) * 32;
    const int rowBase = blockIdx.y * BM, colBase = blockIdx.x * BN;

    float acc[4][4][4];
#pragma unroll
    for (int mi = 0; mi < 4; mi++)
#pragma unroll
        for (int nj = 0; nj < 4; nj++)
#pragma unroll
            for (int r = 0; r < 4; r++) acc[mi][nj][r] = 0.0f;

    auto issue = [&](int kt, int buf) {
        // A tile: gmem [M][K] (k pair-interleaved) -> smem [4][128][8]
        const unsigned* Ag = A + (size_t)rowBase * K + kt;
        unsigned* Ab = As + buf * STAGE;
#pragma unroll
        for (int i = 0; i < 4; i++) {
            int ch = tid + i * 256;        // 1024 chunks
            int kb = ch >> 8;              // 0..3
            int rem = ch & 255;
            int m = rem >> 1, half = rem & 1;
            cpa16(Ab + kb * 1024 + m * 8 + half * 4,
                  Ag + (size_t)m * K + kb * 8 + half * 4);
        }
        // B tile: gmem kperm [K/8][N][8] -> smem [4][128][8] (contiguous rows)
        const unsigned* Wg = W + (size_t)(kt >> 3) * N * 8 + (size_t)colBase * 8;
        unsigned* Bb = Bs + buf * STAGE;
#pragma unroll
        for (int i = 0; i < 4; i++) {
            int ch = tid + i * 256;
            int kb = ch >> 8;
            int cw = ch & 255;
            cpa16(Bb + kb * 1024 + cw * 4, Wg + (size_t)kb * N * 8 + cw * 4);
        }
    };

    issue(0, 0);
    CP_COMMIT();

    const int T = K / BK;
    for (int t = 0; t < T; t++) {
        CP_WAIT0();
        __syncthreads();
        if (t + 1 < T) {
            issue((t + 1) * BK, (t + 1) & 1);
            CP_COMMIT();
        }

        const unsigned* Ab = As + (t & 1) * STAGE;
        const unsigned* Bb = Bs + (t & 1) * STAGE;
#pragma unroll
        for (int ks = 0; ks < 4; ks++) {
            unsigned a[4][4];
#pragma unroll
            for (int mi = 0; mi < 4; mi++) {
                int row = wm + mi * 16 + g;
                uint2 lo = *(const uint2*)(Ab + ks * 1024 + row * 8 + tg * 2);
                uint2 hi = *(const uint2*)(Ab + ks * 1024 + (row + 8) * 8 + tg * 2);
                a[mi][0] = lo.x; a[mi][2] = lo.y;
                a[mi][1] = hi.x; a[mi][3] = hi.y;
            }
#pragma unroll
            for (int nj = 0; nj < 4; nj++) {
                uint2 bb = *(const uint2*)(Bb + ks * 1024 + (wn + nj * 8 + g) * 8 + tg * 2);
#pragma unroll
                for (int mi = 0; mi < 4; mi++)
                    mma_tf32(acc[mi][nj], a[mi][0], a[mi][1], a[mi][2], a[mi][3], bb.x, bb.y);
            }
        }
    }

    // epilogue
#pragma unroll
    for (int nj = 0; nj < 4; nj++) {
        int col = colBase + wn + nj * 8 + 2 * tg;
        float bx, by;
        if (MODE == 5) {
            if (col < HH)            { bx = bias[col];        by = bias[col + 1]; }
            else if (col < HH + 64)  { bx = bias2[col - HH];  by = bias2[col - HH + 1]; }
            else                     { bx = bias3[col - HH - 64]; by = bias3[col - HH - 63]; }
        } else {
            bx = bias[col]; by = bias[col + 1];
        }
#pragma unroll
        for (int mi = 0; mi < 4; mi++) {
            int row = rowBase + wm + mi * 16 + g;
            float v00 = acc[mi][nj][0] + bx, v01 = acc[mi][nj][1] + by;
            float v10 = acc[mi][nj][2] + bx, v11 = acc[mi][nj][3] + by;
            if (MODE == 0) {
                float* o = (float*)Cout;
                *(float2*)(o + (size_t)row * N + col) = make_float2(v00, v01);
                *(float2*)(o + (size_t)(row + 8) * N + col) = make_float2(v10, v11);
            } else {
                if (col < HH) {
                    unsigned* o = (unsigned*)Cout;
                    *(uint2*)(o + (size_t)row * HH + col) =
                        make_uint2(f2tf(v00 * oscale), f2tf(v01 * oscale));
                    *(uint2*)(o + (size_t)(row + 8) * HH + col) =
                        make_uint2(f2tf(v10 * oscale), f2tf(v11 * oscale));
                } else if (col < HH + 64) {
                    unsigned* o = (unsigned*)Cout2;
                    int d = col - HH;
                    o[(size_t)row * HDIM + perm8(d)]           = f2tf(v00);
                    o[(size_t)row * HDIM + perm8(d + 1)]       = f2tf(v01);
                    o[(size_t)(row + 8) * HDIM + perm8(d)]     = f2tf(v10);
                    o[(size_t)(row + 8) * HDIM + perm8(d + 1)] = f2tf(v11);
                } else {
                    unsigned* o = (unsigned*)Cout3;
                    int d = col - HH - 64;
                    o[kperm(row, d, HDIM)]         = f2tf(v00);
                    o[kperm(row, d + 1, HDIM)]     = f2tf(v01);
                    o[kperm(row + 8, d, HDIM)]     = f2tf(v10);
                    o[kperm(row + 8, d + 1, HDIM)] = f2tf(v11);
                }
            }
        }
    }
}

// ---------------------------------------------------------------------------
// MQA flash attention (EXACT round-8 winner, 404us). tf32 mma, no online max.
// Q pre-scaled 0.125*log2e, plain layout. 256 thr / 8 warps, 16 q rows/warp,
// q-tile 128, key tile 64 in two 32-key halves. 2 CTAs/SM.
// grid = (S/128, NH, B).
// ---------------------------------------------------------------------------
__global__ __launch_bounds__(256, 2) void mqa_attn_tc6(
    const unsigned* __restrict__ qp, const unsigned* __restrict__ kp,
    const unsigned* __restrict__ vp, unsigned* __restrict__ outp)
{
    extern __shared__ unsigned sm[];
    unsigned* Ks = sm;                    // [2][64][72]
    unsigned* Vs = sm + 2 * 64 * 72;      // [2][4096]
    unsigned* Ps = Vs + 2 * 4096;         // [8][16][36]

    const int b = blockIdx.z, h = blockIdx.y;
    const int qBase = blockIdx.x * 128;
    const int tid = threadIdx.x, wid = tid >> 5, lane = tid & 31;
    const int g = lane >> 2, tg = lane & 3;

    unsigned qa[8][4];
    {
        int row = qBase + wid * 16 + g;
        const unsigned* q0 = qp + (size_t)(b * SS + row) * HH + h * HDIM;
#pragma unroll
        for (int kf = 0; kf < 8; kf++) {
            int col = kf * 8 + tg;
            qa[kf][0] = __ldg(q0 + col);
            qa[kf][1] = __ldg(q0 + (size_t)8 * HH + col);
            qa[kf][2] = __ldg(q0 + col + 4);
            qa[kf][3] = __ldg(q0 + (size_t)8 * HH + col + 4);
        }
    }

    float o[8][4];
#pragma unroll
    for (int nj = 0; nj < 8; nj++)
#pragma unroll
        for (int r = 0; r < 4; r++) o[nj][r] = 0.0f;
    float lp0 = 0.0f, lp1 = 0.0f;

    auto issue = [&](int t, int buf) {
        const unsigned* kg = kp + (size_t)(b * SS + t * 64) * HDIM;
        unsigned* kb = Ks + buf * 64 * 72;
#pragma unroll
        for (int i = 0; i < 4; i++) {
            int ch = tid + i * 256;
            int r = ch >> 4, cw = ch & 15;
            cpa16(kb + r * 72 + cw * 4, kg + r * 64 + cw * 4);
        }
        const unsigned* vg = vp + (size_t)(b * SS + t * 64) * HDIM;
        unsigned* vb = Vs + buf * 4096;
#pragma unroll
        for (int i = 0; i < 4; i++) {
            int ch = tid + i * 256;
            cpa16(vb + ch * 4, vg + ch * 4);
        }
    };

    issue(0, 0);
    CP_COMMIT();

    unsigned* Pw = Ps + wid * 16 * 36;
    const int T = SS / 64;
    for (int t = 0; t < T; t++) {
        CP_WAIT0();
        __syncthreads();
        if (t + 1 < T) {
            issue(t + 1, (t + 1) & 1);
            CP_COMMIT();
        }

        const unsigned* Kb = Ks + (t & 1) * 64 * 72;
        const unsigned* Vb = Vs + (t & 1) * 4096;

#pragma unroll
        for (int hf = 0; hf < 2; hf++) {
            float s[4][4];
#pragma unroll
            for (int nj = 0; nj < 4; nj++)
#pragma unroll
                for (int r = 0; r < 4; r++) s[nj][r] = 0.0f;
#pragma unroll
            for (int kf = 0; kf < 8; kf++) {
#pragma unroll
                for (int nj = 0; nj < 4; nj++) {
                    uint2 bb = *(const uint2*)(Kb + (hf * 32 + nj * 8 + g) * 72 + kf * 8 + tg * 2);
                    mma_tf32(s[nj], qa[kf][0], qa[kf][1], qa[kf][2], qa[kf][3], bb.x, bb.y);
                }
            }

#pragma unroll
            for (int nj = 0; nj < 4; nj++) {
                float p0 = ex2(s[nj][0]);
                float p1 = ex2(s[nj][1]);
                float p2 = ex2(s[nj][2]);
                float p3 = ex2(s[nj][3]);
                lp0 += p0 + p1;
                lp1 += p2 + p3;
                int col = nj * 8 + 2 * tg;
                *(uint2*)(Pw + g * 36 + col)       = make_uint2(f2tf(p0), f2tf(p1));
                *(uint2*)(Pw + (g + 8) * 36 + col) = make_uint2(f2tf(p2), f2tf(p3));
            }
            __syncwarp();

            unsigned pa[4][4];
#pragma unroll
            for (int kf = 0; kf < 4; kf++) {
                int col = kf * 8 + tg;
                pa[kf][0] = Pw[g * 36 + col];
                pa[kf][1] = Pw[(g + 8) * 36 + col];
                pa[kf][2] = Pw[g * 36 + col + 4];
                pa[kf][3] = Pw[(g + 8) * 36 + col + 4];
            }
#pragma unroll
            for (int nj = 0; nj < 8; nj++) {
#pragma unroll
                for (int kf = 0; kf < 4; kf++) {
                    uint2 bb = *(const uint2*)(Vb + (hf * 4 + kf) * 512 + (nj * 8 + g) * 8 + tg * 2);
                    mma_tf32(o[nj], pa[kf][0], pa[kf][1], pa[kf][2], pa[kf][3], bb.x, bb.y);
                }
            }
            __syncwarp();
        }
    }

    lp0 += __shfl_xor_sync(0xffffffffu, lp0, 1);
    lp0 += __shfl_xor_sync(0xffffffffu, lp0, 2);
    lp1 += __shfl_xor_sync(0xffffffffu, lp1, 1);
    lp1 += __shfl_xor_sync(0xffffffffu, lp1, 2);
    lp0 = 1.0f / lp0;
    lp1 = 1.0f / lp1;

    int row = qBase + wid * 16 + g;
    size_t base = (size_t)(b * SS + row) * HH;
#pragma unroll
    for (int nj = 0; nj < 8; nj++) {
        int cg = h * HDIM + nj * 8 + 2 * tg;
        outp[base + perm8(cg)]                      = f2tf(o[nj][0] * lp0);
        outp[base + perm8(cg + 1)]                  = f2tf(o[nj][1] * lp0);
        outp[base + (size_t)8 * HH + perm8(cg)]     = f2tf(o[nj][2] * lp1);
        outp[base + (size_t)8 * HH + perm8(cg + 1)] = f2tf(o[nj][3] * lp1);
    }
}

// ---------------------------------------------------------------------------
extern "C" void kernel_launch(void* const* d_in, const int* in_sizes, int n_in,
                              void* d_out, int out_size)
{
    const float* X  = (const float*)d_in[0];
    const float* Wq = (const float*)d_in[1];
    const float* bq = (const float*)d_in[2];
    const float* Wk = (const float*)d_in[3];
    const float* bk = (const float*)d_in[4];
    const float* Wv = (const float*)d_in[5];
    const float* bv = (const float*)d_in[6];
    const float* Wo = (const float*)d_in[7];
    const float* bo = (const float*)d_in[8];
    float* out = (float*)d_out;

    unsigned *xp, *wqkv, *wo, *q, *k, *v, *at;
    cudaGetSymbolAddress((void**)&xp,   g_xp);
    cudaGetSymbolAddress((void**)&wqkv, g_wqkv);
    cudaGetSymbolAddress((void**)&wo,   g_wo);
    cudaGetSymbolAddress((void**)&q,    g_q);
    cudaGetSymbolAddress((void**)&k,    g_k);
    cudaGetSymbolAddress((void**)&v,    g_v);
    cudaGetSymbolAddress((void**)&at,   g_at);

    const int smA  = 4 * 4096 * 4;                                  // 65536
    const int smAt = (2 * 64 * 72 + 2 * 4096 + 8 * 16 * 36) * 4;    // 88064

    cudaFuncSetAttribute(gemm_db<0>, cudaFuncAttributeMaxDynamicSharedMemorySize, smA);
    cudaFuncSetAttribute(gemm_db<5>, cudaFuncAttributeMaxDynamicSharedMemorySize, smA);
    cudaFuncSetAttribute(gemm_db<0>, cudaFuncAttributePreferredSharedMemoryCarveout, 100);
    cudaFuncSetAttribute(gemm_db<5>, cudaFuncAttributePreferredSharedMemoryCarveout, 100);
    cudaFuncSetAttribute(mqa_attn_tc6, cudaFuncAttributeMaxDynamicSharedMemorySize, smAt);
    cudaFuncSetAttribute(mqa_attn_tc6, cudaFuncAttributePreferredSharedMemoryCarveout, 100);

    const float qscale = 0.125f * 1.44269504088896340736f;  // 1/sqrt(64) * log2(e)

    // launch 1: X convert
    cvt_x_sh<<<(MM * HH / 4 + 255) / 256, 256>>>((const float4*)X, (uint4*)xp, MM * HH / 4);
    // launch 2: all weight converts
    const int nw = 2 * HH * HH + HH * 128;
    cvt_w_all<<<(nw + 255) / 256, 256>>>(Wq, Wk, Wv, Wo, wqkv, wo);
    // launch 3: fused QKV projection
    gemm_db<5><<<dim3(NQKV / 128, MM / 128), 256, smA>>>(
        xp, wqkv, bq, bk, bv, q, k, v, MM, NQKV, HH, qscale);
    // launch 4 (ncu window): attention
    mqa_attn_tc6<<<dim3(SS / 128, NHEAD, BB), 256, smAt>>>(q, k, v, at);
    // launch 5: output projection
    gemm_db<0><<<dim3(HH / 128, MM / 128), 256, smA>>>(
        at, wo, bo, nullptr, nullptr, out, nullptr, nullptr, MM, HH, HH, 1.0f);
}

// round 11
// speedup vs baseline: 1.6662x; 1.1127x over previous
#include <cuda_runtime.h>
#include <math.h>

#define BB 4
#define SS 2048
#define HH 1024
#define NHEAD 16
#define HDIM 64
#define MM (BB * SS)   // 8192
#define NQKV 1152      // 1024 (Q) + 64 (K) + 64 (V)

// ---------------------------------------------------------------------------
// scratch (__device__ globals; allocation-free)
// ---------------------------------------------------------------------------
__device__ unsigned g_xp[MM * HH];         // X, tf32, pair-interleaved cols
__device__ unsigned g_wqkv[HH * NQKV];     // Wq|Wk|Wv packed, kperm layout
__device__ unsigned g_wo[HH * HH];         // Wo, kperm layout
__device__ unsigned g_q [MM * HH];         // Q, tf32, pre-scaled 0.125*log2e
__device__ unsigned g_k [MM * HDIM];       // K, tf32, pair-interleaved cols
__device__ unsigned g_v [MM * HDIM];       // V, tf32, natural [s/8][d][8]
__device__ unsigned g_at[MM * HH];         // attn out, tf32, pair-interleaved

// ---------------------------------------------------------------------------
// helpers
// ---------------------------------------------------------------------------
__device__ __forceinline__ unsigned f2tf(float f) {
    unsigned u;
    asm("cvt.rna.tf32.f32 %0, %1;" : "=r"(u) : "f"(f));
    return u;
}
__device__ __forceinline__ float ex2(float f) {
    float r;
    asm("ex2.approx.f32 %0, %1;" : "=f"(r) : "f"(f));
    return r;
}
__device__ __forceinline__ int perm8(int c) {
    return (c & ~7) | ((c & 3) << 1) | ((c >> 2) & 1);
}
__device__ __forceinline__ size_t kperm(int k, int n, int N) {
    return (size_t)(k >> 3) * N * 8 + n * 8 + (k & 3) * 2 + ((k >> 2) & 1);
}
// natural V layout: key s, dim d -> word (s/8)*512 + d*8 + (s%8)
__device__ __forceinline__ size_t vnat(int s, int d) {
    return (size_t)(s >> 3) * (HDIM * 8) + d * 8 + (s & 7);
}
__device__ __forceinline__ void mma_tf32(float c[4],
                                         unsigned a0, unsigned a1,
                                         unsigned a2, unsigned a3,
                                         unsigned b0, unsigned b1) {
    asm volatile(
        "mma.sync.aligned.m16n8k8.row.col.f32.tf32.tf32.f32 "
        "{%0,%1,%2,%3}, {%4,%5,%6,%7}, {%8,%9}, {%0,%1,%2,%3};"
        : "+f"(c[0]), "+f"(c[1]), "+f"(c[2]), "+f"(c[3])
        : "r"(a0), "r"(a1), "r"(a2), "r"(a3), "r"(b0), "r"(b1));
}
__device__ __forceinline__ void cpa16(unsigned* smem_dst, const unsigned* gmem_src) {
    unsigned s = (unsigned)__cvta_generic_to_shared(smem_dst);
    asm volatile("cp.async.cg.shared.global [%0], [%1], 16;" :: "r"(s), "l"(gmem_src));
}
#define CP_COMMIT() asm volatile("cp.async.commit_group;")
#define CP_WAIT0()  asm volatile("cp.async.wait_group 0;")

// ---------------------------------------------------------------------------
// pre-convert kernels (2 launches)
// ---------------------------------------------------------------------------
__global__ void cvt_x_sh(const float4* __restrict__ in, uint4* __restrict__ out, int n4) {
    int idx = blockIdx.x * 256 + threadIdx.x;
    if (idx < n4) {
        float4 v = in[idx];
        unsigned x0 = f2tf(v.x), x1 = f2tf(v.y), x2 = f2tf(v.z), x3 = f2tf(v.w);
        bool odd = threadIdx.x & 1;
        unsigned a = odd ? x0 : x2;
        unsigned b = odd ? x1 : x3;
        unsigned sa = __shfl_xor_sync(0xffffffffu, a, 1);
        unsigned sb = __shfl_xor_sync(0xffffffffu, b, 1);
        uint4 o;
        if (!odd) { o.x = x0; o.y = sa; o.z = x1; o.w = sb; }
        else      { o.x = sa; o.y = x2; o.z = sb; o.w = x3; }
        out[idx] = o;
    }
}
__global__ void cvt_w_all(const float* __restrict__ Wq, const float* __restrict__ Wk,
                          const float* __restrict__ Wv, const float* __restrict__ Wo,
                          unsigned* __restrict__ wqkv, unsigned* __restrict__ wo)
{
    int i = blockIdx.x * 256 + threadIdx.x;
    if (i < HH * HH) {
        int nn = i & (HH - 1), k = i >> 10;
        wqkv[kperm(k, nn, NQKV)] = f2tf(Wq[i]);
    } else if (i < HH * HH + HH * 128) {
        int j = i - HH * HH;
        int nn = j & 127, k = j >> 7;
        float v = (nn < HDIM) ? Wk[k * HDIM + nn] : Wv[k * HDIM + nn - HDIM];
        wqkv[kperm(k, HH + nn, NQKV)] = f2tf(v);
    } else if (i < 2 * HH * HH + HH * 128) {
        int j = i - HH * HH - HH * 128;
        int nn = j & (HH - 1), k = j >> 10;
        wo[kperm(k, nn, HH)] = f2tf(Wo[j]);
    }
}

// ---------------------------------------------------------------------------
// double-buffered tf32 GEMM (round-8 config). A: pair-interleaved cols [M][K].
// W: kperm [K/8][N][8]. MODE 0: fp32+bias -> final out. MODE 5: QKV routing.
// BM=256, BN=128, BK=32, 256 threads, 8 warps (4m x 2n), warp tile 64x64.
// ---------------------------------------------------------------------------
template <int MODE>
__global__ __launch_bounds__(256) void gemm_db(
    const unsigned* __restrict__ A, const unsigned* __restrict__ W,
    const float* __restrict__ bias, const float* __restrict__ bias2,
    const float* __restrict__ bias3,
    void* __restrict__ Cout, void* __restrict__ Cout2, void* __restrict__ Cout3,
    int M, int N, int K, float oscale)
{
    constexpr int BM = 256, BN = 128, BK = 32;
    constexpr int NTHR = 256;
    constexpr int AST = 40;
    constexpr int BWORDS = 4 * BN * 8;

    extern __shared__ unsigned sm[];
    unsigned* As = sm;
    unsigned* Bs = sm + 2 * BM * AST;

    const int tid = threadIdx.x;
    const int wid = tid >> 5, lane = tid & 31, g = lane >> 2, tg = lane & 3;
    const int wm = (wid >> 1) * 64;
    const int wn = (wid & 1) * 64;
    const int rowBase = blockIdx.y * BM, colBase = blockIdx.x * BN;

    float acc[4][8][4];
#pragma unroll
    for (int mi = 0; mi < 4; mi++)
#pragma unroll
        for (int nj = 0; nj < 8; nj++)
#pragma unroll
            for (int r = 0; r < 4; r++) acc[mi][nj][r] = 0.0f;

    auto issue = [&](int kt, int buf) {
        const unsigned* Ag = A + (size_t)rowBase * K + kt;
        unsigned* Ab = As + buf * BM * AST;
#pragma unroll
        for (int i = 0; i < (BM * BK / 4) / NTHR; i++) {
            int ch = tid + i * NTHR;
            int r = ch >> 3, cw = ch & 7;
            cpa16(Ab + r * AST + cw * 4, Ag + (size_t)r * K + cw * 4);
        }
        const unsigned* Wg = W + (size_t)(kt >> 3) * N * 8 + (size_t)colBase * 8;
        unsigned* Bb = Bs + buf * BWORDS;
#pragma unroll
        for (int i = 0; i < (BWORDS / 4) / NTHR; i++) {
            int ch = tid + i * NTHR;
            int r = ch / (BN * 2), cw = ch % (BN * 2);
            cpa16(Bb + r * BN * 8 + cw * 4, Wg + (size_t)r * N * 8 + cw * 4);
        }
    };

    issue(0, 0);
    CP_COMMIT();

    const int T = K / BK;
    for (int t = 0; t < T; t++) {
        CP_WAIT0();
        __syncthreads();
        if (t + 1 < T) {
            issue((t + 1) * BK, (t + 1) & 1);
            CP_COMMIT();
        }

        const unsigned* Ab = As + (t & 1) * BM * AST;
        const unsigned* Bb = Bs + (t & 1) * BWORDS;
#pragma unroll
        for (int ks = 0; ks < 4; ks++) {
            unsigned a[4][4];
#pragma unroll
            for (int mi = 0; mi < 4; mi++) {
                int row = wm + mi * 16 + g;
                uint2 lo = *(const uint2*)(Ab + row * AST + ks * 8 + tg * 2);
                uint2 hi = *(const uint2*)(Ab + (row + 8) * AST + ks * 8 + tg * 2);
                a[mi][0] = lo.x; a[mi][2] = lo.y;
                a[mi][1] = hi.x; a[mi][3] = hi.y;
            }
#pragma unroll
            for (int nj = 0; nj < 8; nj++) {
                uint2 bb = *(const uint2*)(Bb + ks * BN * 8 + (wn + nj * 8 + g) * 8 + tg * 2);
#pragma unroll
                for (int mi = 0; mi < 4; mi++)
                    mma_tf32(acc[mi][nj], a[mi][0], a[mi][1], a[mi][2], a[mi][3], bb.x, bb.y);
            }
        }
    }

#pragma unroll
    for (int nj = 0; nj < 8; nj++) {
        int col = colBase + wn + nj * 8 + 2 * tg;
        float bx, by;
        if (MODE == 5) {
            if (col < HH)            { bx = bias[col];        by = bias[col + 1]; }
            else if (col < HH + 64)  { bx = bias2[col - HH];  by = bias2[col - HH + 1]; }
            else                     { bx = bias3[col - HH - 64]; by = bias3[col - HH - 63]; }
        } else {
            bx = bias[col]; by = bias[col + 1];
        }
#pragma unroll
        for (int mi = 0; mi < 4; mi++) {
            int row = rowBase + wm + mi * 16 + g;
            float v00 = acc[mi][nj][0] + bx, v01 = acc[mi][nj][1] + by;
            float v10 = acc[mi][nj][2] + bx, v11 = acc[mi][nj][3] + by;
            if (MODE == 0) {
                float* o = (float*)Cout;
                *(float2*)(o + (size_t)row * N + col) = make_float2(v00, v01);
                *(float2*)(o + (size_t)(row + 8) * N + col) = make_float2(v10, v11);
            } else {
                if (col < HH) {
                    unsigned* o = (unsigned*)Cout;
                    *(uint2*)(o + (size_t)row * HH + col) =
                        make_uint2(f2tf(v00 * oscale), f2tf(v01 * oscale));
                    *(uint2*)(o + (size_t)(row + 8) * HH + col) =
                        make_uint2(f2tf(v10 * oscale), f2tf(v11 * oscale));
                } else if (col < HH + 64) {
                    unsigned* o = (unsigned*)Cout2;
                    int d = col - HH;
                    o[(size_t)row * HDIM + perm8(d)]           = f2tf(v00);
                    o[(size_t)row * HDIM + perm8(d + 1)]       = f2tf(v01);
                    o[(size_t)(row + 8) * HDIM + perm8(d)]     = f2tf(v10);
                    o[(size_t)(row + 8) * HDIM + perm8(d + 1)] = f2tf(v11);
                } else {
                    // V: natural [s/8][d][8] layout
                    unsigned* o = (unsigned*)Cout3;
                    int d = col - HH - 64;
                    o[vnat(row, d)]         = f2tf(v00);
                    o[vnat(row, d + 1)]     = f2tf(v01);
                    o[vnat(row + 8, d)]     = f2tf(v10);
                    o[vnat(row + 8, d + 1)] = f2tf(v11);
                }
            }
        }
    }
}

// ---------------------------------------------------------------------------
// MQA flash attention v8: no P smem round-trip. The S C-fragment feeds the
// PV A-fragment directly (a0=c0, a1=c2, a2=c1, a3=c3); with V stored in
// natural key order this is exact. tf32 mma, no online max, Q pre-scaled.
// 256 thr / 8 warps, 16 q rows/warp, q-tile 128, key tile 64 (two halves).
// 2 CTAs/SM (smem ~70KB, regs <=128). grid = (S/128, NH, B).
// ---------------------------------------------------------------------------
__global__ __launch_bounds__(256, 2) void mqa_attn_tc8(
    const unsigned* __restrict__ qp, const unsigned* __restrict__ kp,
    const unsigned* __restrict__ vp, unsigned* __restrict__ outp)
{
    extern __shared__ unsigned sm[];
    unsigned* Ks = sm;                    // [2][64][72]
    unsigned* Vs = sm + 2 * 64 * 72;      // [2][4096]

    const int b = blockIdx.z, h = blockIdx.y;
    const int qBase = blockIdx.x * 128;
    const int tid = threadIdx.x, wid = tid >> 5, lane = tid & 31;
    const int g = lane >> 2, tg = lane & 3;

    unsigned qa[8][4];
    {
        int row = qBase + wid * 16 + g;
        const unsigned* q0 = qp + (size_t)(b * SS + row) * HH + h * HDIM;
#pragma unroll
        for (int kf = 0; kf < 8; kf++) {
            int col = kf * 8 + tg;
            qa[kf][0] = __ldg(q0 + col);
            qa[kf][1] = __ldg(q0 + (size_t)8 * HH + col);
            qa[kf][2] = __ldg(q0 + col + 4);
            qa[kf][3] = __ldg(q0 + (size_t)8 * HH + col + 4);
        }
    }

    float o[8][4];
#pragma unroll
    for (int nj = 0; nj < 8; nj++)
#pragma unroll
        for (int r = 0; r < 4; r++) o[nj][r] = 0.0f;
    float lp0 = 0.0f, lp1 = 0.0f;

    auto issue = [&](int t, int buf) {
        const unsigned* kg = kp + (size_t)(b * SS + t * 64) * HDIM;
        unsigned* kb = Ks + buf * 64 * 72;
#pragma unroll
        for (int i = 0; i < 4; i++) {
            int ch = tid + i * 256;
            int r = ch >> 4, cw = ch & 15;
            cpa16(kb + r * 72 + cw * 4, kg + r * 64 + cw * 4);
        }
        const unsigned* vg = vp + (size_t)(b * SS + t * 64) * HDIM;  // natural flat
        unsigned* vb = Vs + buf * 4096;
#pragma unroll
        for (int i = 0; i < 4; i++) {
            int ch = tid + i * 256;
            cpa16(vb + ch * 4, vg + ch * 4);
        }
    };

    issue(0, 0);
    CP_COMMIT();

    const int T = SS / 64;
    for (int t = 0; t < T; t++) {
        CP_WAIT0();
        __syncthreads();
        if (t + 1 < T) {
            issue(t + 1, (t + 1) & 1);
            CP_COMMIT();
        }

        const unsigned* Kb = Ks + (t & 1) * 64 * 72;
        const unsigned* Vb = Vs + (t & 1) * 4096;

#pragma unroll
        for (int hf = 0; hf < 2; hf++) {
            // S = Q K^T  (16 q x 32 keys per warp)
            float s[4][4];
#pragma unroll
            for (int nj = 0; nj < 4; nj++)
#pragma unroll
                for (int r = 0; r < 4; r++) s[nj][r] = 0.0f;
#pragma unroll
            for (int kf = 0; kf < 8; kf++) {
#pragma unroll
                for (int nj = 0; nj < 4; nj++) {
                    uint2 bb = *(const uint2*)(Kb + (hf * 32 + nj * 8 + g) * 72 + kf * 8 + tg * 2);
                    mma_tf32(s[nj], qa[kf][0], qa[kf][1], qa[kf][2], qa[kf][3], bb.x, bb.y);
                }
            }

            // P = 2^S directly into PV A-fragments (no smem round trip):
            // a0 = P[g][key 2tg], a1 = P[g+8][key 2tg], a2 = P[g][2tg+1], a3 = P[g+8][2tg+1]
            unsigned pa[4][4];
#pragma unroll
            for (int nj = 0; nj < 4; nj++) {
                float p0 = ex2(s[nj][0]);
                float p1 = ex2(s[nj][1]);
                float p2 = ex2(s[nj][2]);
                float p3 = ex2(s[nj][3]);
                lp0 += p0 + p1;
                lp1 += p2 + p3;
                pa[nj][0] = f2tf(p0);
                pa[nj][1] = f2tf(p2);
                pa[nj][2] = f2tf(p1);
                pa[nj][3] = f2tf(p3);
            }

            // O += P V  (V natural key order; chunk kf covers keys hf*32+kf*8..+8)
#pragma unroll
            for (int nj = 0; nj < 8; nj++) {
#pragma unroll
                for (int kf = 0; kf < 4; kf++) {
                    uint2 bb = *(const uint2*)(Vb + (hf * 4 + kf) * 512 + (nj * 8 + g) * 8 + tg * 2);
                    mma_tf32(o[nj], pa[kf][0], pa[kf][1], pa[kf][2], pa[kf][3], bb.x, bb.y);
                }
            }
        }
    }

    lp0 += __shfl_xor_sync(0xffffffffu, lp0, 1);
    lp0 += __shfl_xor_sync(0xffffffffu, lp0, 2);
    lp1 += __shfl_xor_sync(0xffffffffu, lp1, 1);
    lp1 += __shfl_xor_sync(0xffffffffu, lp1, 2);
    lp0 = 1.0f / lp0;
    lp1 = 1.0f / lp1;

    int row = qBase + wid * 16 + g;
    size_t base = (size_t)(b * SS + row) * HH;
#pragma unroll
    for (int nj = 0; nj < 8; nj++) {
        int cg = h * HDIM + nj * 8 + 2 * tg;
        outp[base + perm8(cg)]                      = f2tf(o[nj][0] * lp0);
        outp[base + perm8(cg + 1)]                  = f2tf(o[nj][1] * lp0);
        outp[base + (size_t)8 * HH + perm8(cg)]     = f2tf(o[nj][2] * lp1);
        outp[base + (size_t)8 * HH + perm8(cg + 1)] = f2tf(o[nj][3] * lp1);
    }
}

// ---------------------------------------------------------------------------
extern "C" void kernel_launch(void* const* d_in, const int* in_sizes, int n_in,
                              void* d_out, int out_size)
{
    const float* X  = (const float*)d_in[0];
    const float* Wq = (const float*)d_in[1];
    const float* bq = (const float*)d_in[2];
    const float* Wk = (const float*)d_in[3];
    const float* bk = (const float*)d_in[4];
    const float* Wv = (const float*)d_in[5];
    const float* bv = (const float*)d_in[6];
    const float* Wo = (const float*)d_in[7];
    const float* bo = (const float*)d_in[8];
    float* out = (float*)d_out;

    unsigned *xp, *wqkv, *wo, *q, *k, *v, *at;
    cudaGetSymbolAddress((void**)&xp,   g_xp);
    cudaGetSymbolAddress((void**)&wqkv, g_wqkv);
    cudaGetSymbolAddress((void**)&wo,   g_wo);
    cudaGetSymbolAddress((void**)&q,    g_q);
    cudaGetSymbolAddress((void**)&k,    g_k);
    cudaGetSymbolAddress((void**)&v,    g_v);
    cudaGetSymbolAddress((void**)&at,   g_at);

    const int smA  = (2 * 256 * 40 + 2 * 4 * 128 * 8) * 4;   // 114688
    const int smAt = (2 * 64 * 72 + 2 * 4096) * 4;           // 69632

    cudaFuncSetAttribute(gemm_db<0>, cudaFuncAttributeMaxDynamicSharedMemorySize, smA);
    cudaFuncSetAttribute(gemm_db<5>, cudaFuncAttributeMaxDynamicSharedMemorySize, smA);
    cudaFuncSetAttribute(mqa_attn_tc8, cudaFuncAttributeMaxDynamicSharedMemorySize, smAt);
    cudaFuncSetAttribute(mqa_attn_tc8, cudaFuncAttributePreferredSharedMemoryCarveout, 100);

    const float qscale = 0.125f * 1.44269504088896340736f;  // 1/sqrt(64) * log2(e)

    // launch 1: X convert
    cvt_x_sh<<<(MM * HH / 4 + 255) / 256, 256>>>((const float4*)X, (uint4*)xp, MM * HH / 4);
    // launch 2: all weight converts
    const int nw = 2 * HH * HH + HH * 128;
    cvt_w_all<<<(nw + 255) / 256, 256>>>(Wq, Wk, Wv, Wo, wqkv, wo);
    // launch 3: fused QKV projection
    gemm_db<5><<<dim3(NQKV / 128, MM / 256), 256, smA>>>(
        xp, wqkv, bq, bk, bv, q, k, v, MM, NQKV, HH, qscale);
    // launch 4 (ncu window): attention
    mqa_attn_tc8<<<dim3(SS / 128, NHEAD, BB), 256, smAt>>>(q, k, v, at);
    // launch 5: output projection
    gemm_db<0><<<dim3(HH / 128, MM / 256), 256, smA>>>(
        at, wo, bo, nullptr, nullptr, out, nullptr, nullptr, MM, HH, HH, 1.0f);
}

// round 12
// speedup vs baseline: 1.7406x; 1.0447x over previous
#include <cuda_runtime.h>
#include <math.h>

#define BB 4
#define SS 2048
#define HH 1024
#define NHEAD 16
#define HDIM 64
#define MM (BB * SS)   // 8192
#define NQKV 1152      // 1024 (Q) + 64 (K) + 64 (V)

// ---------------------------------------------------------------------------
// scratch (__device__ globals; allocation-free)
// ---------------------------------------------------------------------------
__device__ unsigned g_xp[MM * HH];         // X, tf32, pair-interleaved cols
__device__ unsigned g_wqkv[HH * NQKV];     // Wq|Wk|Wv packed, kperm layout
__device__ unsigned g_wo[HH * HH];         // Wo, kperm layout
__device__ unsigned g_q [MM * HH];         // Q, tf32, pre-scaled 0.125*log2e (plain)
__device__ unsigned g_k [MM * HDIM];       // K, tf32, pair-interleaved cols
__device__ unsigned g_v [MM * HDIM];       // V, tf32, natural [s/8][d][8]
__device__ unsigned g_at[MM * HH];         // attn out, tf32, pair-interleaved

// ---------------------------------------------------------------------------
// helpers
// ---------------------------------------------------------------------------
__device__ __forceinline__ unsigned f2tf(float f) {
    unsigned u;
    asm("cvt.rna.tf32.f32 %0, %1;" : "=r"(u) : "f"(f));
    return u;
}
__device__ __forceinline__ float ex2(float f) {
    float r;
    asm("ex2.approx.f32 %0, %1;" : "=f"(r) : "f"(f));
    return r;
}
__device__ __forceinline__ int perm8(int c) {
    return (c & ~7) | ((c & 3) << 1) | ((c >> 2) & 1);
}
__device__ __forceinline__ size_t kperm(int k, int n, int N) {
    return (size_t)(k >> 3) * N * 8 + n * 8 + (k & 3) * 2 + ((k >> 2) & 1);
}
// natural V layout: key s, dim d -> word (s/8)*512 + d*8 + (s%8)
__device__ __forceinline__ size_t vnat(int s, int d) {
    return (size_t)(s >> 3) * (HDIM * 8) + d * 8 + (s & 7);
}
__device__ __forceinline__ void mma_tf32(float c[4],
                                         unsigned a0, unsigned a1,
                                         unsigned a2, unsigned a3,
                                         unsigned b0, unsigned b1) {
    asm volatile(
        "mma.sync.aligned.m16n8k8.row.col.f32.tf32.tf32.f32 "
        "{%0,%1,%2,%3}, {%4,%5,%6,%7}, {%8,%9}, {%0,%1,%2,%3};"
        : "+f"(c[0]), "+f"(c[1]), "+f"(c[2]), "+f"(c[3])
        : "r"(a0), "r"(a1), "r"(a2), "r"(a3), "r"(b0), "r"(b1));
}
__device__ __forceinline__ void cpa16(unsigned* smem_dst, const unsigned* gmem_src) {
    unsigned s = (unsigned)__cvta_generic_to_shared(smem_dst);
    asm volatile("cp.async.cg.shared.global [%0], [%1], 16;" :: "r"(s), "l"(gmem_src));
}
#define CP_COMMIT() asm volatile("cp.async.commit_group;")
#define CP_WAIT0()  asm volatile("cp.async.wait_group 0;")

// ---------------------------------------------------------------------------
// pre-convert kernels (2 launches)
// ---------------------------------------------------------------------------
__global__ void cvt_x_sh(const float4* __restrict__ in, uint4* __restrict__ out, int n4) {
    int idx = blockIdx.x * 256 + threadIdx.x;
    if (idx < n4) {
        float4 v = in[idx];
        unsigned x0 = f2tf(v.x), x1 = f2tf(v.y), x2 = f2tf(v.z), x3 = f2tf(v.w);
        bool odd = threadIdx.x & 1;
        unsigned a = odd ? x0 : x2;
        unsigned b = odd ? x1 : x3;
        unsigned sa = __shfl_xor_sync(0xffffffffu, a, 1);
        unsigned sb = __shfl_xor_sync(0xffffffffu, b, 1);
        uint4 o;
        if (!odd) { o.x = x0; o.y = sa; o.z = x1; o.w = sb; }
        else      { o.x = sa; o.y = x2; o.z = sb; o.w = x3; }
        out[idx] = o;
    }
}
__global__ void cvt_w_all(const float* __restrict__ Wq, const float* __restrict__ Wk,
                          const float* __restrict__ Wv, const float* __restrict__ Wo,
                          unsigned* __restrict__ wqkv, unsigned* __restrict__ wo)
{
    int i = blockIdx.x * 256 + threadIdx.x;
    if (i < HH * HH) {
        int nn = i & (HH - 1), k = i >> 10;
        wqkv[kperm(k, nn, NQKV)] = f2tf(Wq[i]);
    } else if (i < HH * HH + HH * 128) {
        int j = i - HH * HH;
        int nn = j & 127, k = j >> 7;
        float v = (nn < HDIM) ? Wk[k * HDIM + nn] : Wv[k * HDIM + nn - HDIM];
        wqkv[kperm(k, HH + nn, NQKV)] = f2tf(v);
    } else if (i < 2 * HH * HH + HH * 128) {
        int j = i - HH * HH - HH * 128;
        int nn = j & (HH - 1), k = j >> 10;
        wo[kperm(k, nn, HH)] = f2tf(Wo[j]);
    }
}

// ---------------------------------------------------------------------------
// double-buffered tf32 GEMM (round-8 config, unchanged).
// ---------------------------------------------------------------------------
template <int MODE>
__global__ __launch_bounds__(256) void gemm_db(
    const unsigned* __restrict__ A, const unsigned* __restrict__ W,
    const float* __restrict__ bias, const float* __restrict__ bias2,
    const float* __restrict__ bias3,
    void* __restrict__ Cout, void* __restrict__ Cout2, void* __restrict__ Cout3,
    int M, int N, int K, float oscale)
{
    constexpr int BM = 256, BN = 128, BK = 32;
    constexpr int NTHR = 256;
    constexpr int AST = 40;
    constexpr int BWORDS = 4 * BN * 8;

    extern __shared__ unsigned sm[];
    unsigned* As = sm;
    unsigned* Bs = sm + 2 * BM * AST;

    const int tid = threadIdx.x;
    const int wid = tid >> 5, lane = tid & 31, g = lane >> 2, tg = lane & 3;
    const int wm = (wid >> 1) * 64;
    const int wn = (wid & 1) * 64;
    const int rowBase = blockIdx.y * BM, colBase = blockIdx.x * BN;

    float acc[4][8][4];
#pragma unroll
    for (int mi = 0; mi < 4; mi++)
#pragma unroll
        for (int nj = 0; nj < 8; nj++)
#pragma unroll
            for (int r = 0; r < 4; r++) acc[mi][nj][r] = 0.0f;

    auto issue = [&](int kt, int buf) {
        const unsigned* Ag = A + (size_t)rowBase * K + kt;
        unsigned* Ab = As + buf * BM * AST;
#pragma unroll
        for (int i = 0; i < (BM * BK / 4) / NTHR; i++) {
            int ch = tid + i * NTHR;
            int r = ch >> 3, cw = ch & 7;
            cpa16(Ab + r * AST + cw * 4, Ag + (size_t)r * K + cw * 4);
        }
        const unsigned* Wg = W + (size_t)(kt >> 3) * N * 8 + (size_t)colBase * 8;
        unsigned* Bb = Bs + buf * BWORDS;
#pragma unroll
        for (int i = 0; i < (BWORDS / 4) / NTHR; i++) {
            int ch = tid + i * NTHR;
            int r = ch / (BN * 2), cw = ch % (BN * 2);
            cpa16(Bb + r * BN * 8 + cw * 4, Wg + (size_t)r * N * 8 + cw * 4);
        }
    };

    issue(0, 0);
    CP_COMMIT();

    const int T = K / BK;
    for (int t = 0; t < T; t++) {
        CP_WAIT0();
        __syncthreads();
        if (t + 1 < T) {
            issue((t + 1) * BK, (t + 1) & 1);
            CP_COMMIT();
        }

        const unsigned* Ab = As + (t & 1) * BM * AST;
        const unsigned* Bb = Bs + (t & 1) * BWORDS;
#pragma unroll
        for (int ks = 0; ks < 4; ks++) {
            unsigned a[4][4];
#pragma unroll
            for (int mi = 0; mi < 4; mi++) {
                int row = wm + mi * 16 + g;
                uint2 lo = *(const uint2*)(Ab + row * AST + ks * 8 + tg * 2);
                uint2 hi = *(const uint2*)(Ab + (row + 8) * AST + ks * 8 + tg * 2);
                a[mi][0] = lo.x; a[mi][2] = lo.y;
                a[mi][1] = hi.x; a[mi][3] = hi.y;
            }
#pragma unroll
            for (int nj = 0; nj < 8; nj++) {
                uint2 bb = *(const uint2*)(Bb + ks * BN * 8 + (wn + nj * 8 + g) * 8 + tg * 2);
#pragma unroll
                for (int mi = 0; mi < 4; mi++)
                    mma_tf32(acc[mi][nj], a[mi][0], a[mi][1], a[mi][2], a[mi][3], bb.x, bb.y);
            }
        }
    }

#pragma unroll
    for (int nj = 0; nj < 8; nj++) {
        int col = colBase + wn + nj * 8 + 2 * tg;
        float bx, by;
        if (MODE == 5) {
            if (col < HH)            { bx = bias[col];        by = bias[col + 1]; }
            else if (col < HH + 64)  { bx = bias2[col - HH];  by = bias2[col - HH + 1]; }
            else                     { bx = bias3[col - HH - 64]; by = bias3[col - HH - 63]; }
        } else {
            bx = bias[col]; by = bias[col + 1];
        }
#pragma unroll
        for (int mi = 0; mi < 4; mi++) {
            int row = rowBase + wm + mi * 16 + g;
            float v00 = acc[mi][nj][0] + bx, v01 = acc[mi][nj][1] + by;
            float v10 = acc[mi][nj][2] + bx, v11 = acc[mi][nj][3] + by;
            if (MODE == 0) {
                float* o = (float*)Cout;
                *(float2*)(o + (size_t)row * N + col) = make_float2(v00, v01);
                *(float2*)(o + (size_t)(row + 8) * N + col) = make_float2(v10, v11);
            } else {
                if (col < HH) {
                    unsigned* o = (unsigned*)Cout;
                    *(uint2*)(o + (size_t)row * HH + col) =
                        make_uint2(f2tf(v00 * oscale), f2tf(v01 * oscale));
                    *(uint2*)(o + (size_t)(row + 8) * HH + col) =
                        make_uint2(f2tf(v10 * oscale), f2tf(v11 * oscale));
                } else if (col < HH + 64) {
                    unsigned* o = (unsigned*)Cout2;
                    int d = col - HH;
                    o[(size_t)row * HDIM + perm8(d)]           = f2tf(v00);
                    o[(size_t)row * HDIM + perm8(d + 1)]       = f2tf(v01);
                    o[(size_t)(row + 8) * HDIM + perm8(d)]     = f2tf(v10);
                    o[(size_t)(row + 8) * HDIM + perm8(d + 1)] = f2tf(v11);
                } else {
                    unsigned* o = (unsigned*)Cout3;
                    int d = col - HH - 64;
                    o[vnat(row, d)]         = f2tf(v00);
                    o[vnat(row, d + 1)]     = f2tf(v01);
                    o[vnat(row + 8, d)]     = f2tf(v10);
                    o[vnat(row + 8, d + 1)] = f2tf(v11);
                }
            }
        }
    }
}

// ---------------------------------------------------------------------------
// MQA flash attention v9: 128-thread CTAs -> 256 regs/thread at 2 CTAs/SM.
// 2 m-frags/warp with Q register-resident: every K/V B-frag LDS.64 feeds
// 2 MMAs (1.0 wavefront/MMA, half of v8). S C-frag feeds PV A-frag directly
// (V natural key order). No online max, Q pre-scaled 0.125*log2e.
// 4 warps x 32 q rows = q-tile 128, key tile 64 (two 32-key halves).
// grid = (S/128, NH, B).
// ---------------------------------------------------------------------------
__global__ __launch_bounds__(128, 2) void mqa_attn_tc9(
    const unsigned* __restrict__ qp, const unsigned* __restrict__ kp,
    const unsigned* __restrict__ vp, unsigned* __restrict__ outp)
{
    extern __shared__ unsigned sm[];
    unsigned* Ks = sm;                    // [2][64][72]
    unsigned* Vs = sm + 2 * 64 * 72;      // [2][4096]

    const int b = blockIdx.z, h = blockIdx.y;
    const int qBase = blockIdx.x * 128;
    const int tid = threadIdx.x, wid = tid >> 5, lane = tid & 31;
    const int g = lane >> 2, tg = lane & 3;

    // Q fragments register-resident: warp owns rows wid*32 + mi*16 + {g, g+8}
    unsigned qa[2][8][4];
#pragma unroll
    for (int mi = 0; mi < 2; mi++) {
        int row = qBase + wid * 32 + mi * 16 + g;
        const unsigned* q0 = qp + (size_t)(b * SS + row) * HH + h * HDIM;
#pragma unroll
        for (int kf = 0; kf < 8; kf++) {
            int col = kf * 8 + tg;
            qa[mi][kf][0] = __ldg(q0 + col);
            qa[mi][kf][1] = __ldg(q0 + (size_t)8 * HH + col);
            qa[mi][kf][2] = __ldg(q0 + col + 4);
            qa[mi][kf][3] = __ldg(q0 + (size_t)8 * HH + col + 4);
        }
    }

    float o[2][8][4];
#pragma unroll
    for (int mi = 0; mi < 2; mi++)
#pragma unroll
        for (int nj = 0; nj < 8; nj++)
#pragma unroll
            for (int r = 0; r < 4; r++) o[mi][nj][r] = 0.0f;
    float lp[4] = {0.0f, 0.0f, 0.0f, 0.0f};

    auto issue = [&](int t, int buf) {
        const unsigned* kg = kp + (size_t)(b * SS + t * 64) * HDIM;
        unsigned* kb = Ks + buf * 64 * 72;
#pragma unroll
        for (int i = 0; i < 8; i++) {
            int ch = tid + i * 128;
            int r = ch >> 4, cw = ch & 15;
            cpa16(kb + r * 72 + cw * 4, kg + r * 64 + cw * 4);
        }
        const unsigned* vg = vp + (size_t)(b * SS + t * 64) * HDIM;  // natural flat
        unsigned* vb = Vs + buf * 4096;
#pragma unroll
        for (int i = 0; i < 8; i++) {
            int ch = tid + i * 128;
            cpa16(vb + ch * 4, vg + ch * 4);
        }
    };

    issue(0, 0);
    CP_COMMIT();

    const int T = SS / 64;
    for (int t = 0; t < T; t++) {
        CP_WAIT0();
        __syncthreads();
        if (t + 1 < T) {
            issue(t + 1, (t + 1) & 1);
            CP_COMMIT();
        }

        const unsigned* Kb = Ks + (t & 1) * 64 * 72;
        const unsigned* Vb = Vs + (t & 1) * 4096;

#pragma unroll
        for (int hf = 0; hf < 2; hf++) {
            // S = Q K^T  (32 q x 32 keys per warp; each K B-frag -> 2 MMAs)
            float s[2][4][4];
#pragma unroll
            for (int mi = 0; mi < 2; mi++)
#pragma unroll
                for (int nj = 0; nj < 4; nj++)
#pragma unroll
                    for (int r = 0; r < 4; r++) s[mi][nj][r] = 0.0f;
#pragma unroll
            for (int kf = 0; kf < 8; kf++) {
#pragma unroll
                for (int nj = 0; nj < 4; nj++) {
                    uint2 bb = *(const uint2*)(Kb + (hf * 32 + nj * 8 + g) * 72 + kf * 8 + tg * 2);
                    mma_tf32(s[0][nj], qa[0][kf][0], qa[0][kf][1], qa[0][kf][2], qa[0][kf][3], bb.x, bb.y);
                    mma_tf32(s[1][nj], qa[1][kf][0], qa[1][kf][1], qa[1][kf][2], qa[1][kf][3], bb.x, bb.y);
                }
            }

            // P = 2^S directly into PV A-fragments (a0=c0, a1=c2, a2=c1, a3=c3)
            unsigned pa[2][4][4];
#pragma unroll
            for (int mi = 0; mi < 2; mi++)
#pragma unroll
                for (int nj = 0; nj < 4; nj++) {
                    float p0 = ex2(s[mi][nj][0]);
                    float p1 = ex2(s[mi][nj][1]);
                    float p2 = ex2(s[mi][nj][2]);
                    float p3 = ex2(s[mi][nj][3]);
                    lp[mi * 2 + 0] += p0 + p1;
                    lp[mi * 2 + 1] += p2 + p3;
                    pa[mi][nj][0] = f2tf(p0);
                    pa[mi][nj][1] = f2tf(p2);
                    pa[mi][nj][2] = f2tf(p1);
                    pa[mi][nj][3] = f2tf(p3);
                }

            // O += P V  (each V B-frag -> 2 MMAs)
#pragma unroll
            for (int nj = 0; nj < 8; nj++) {
#pragma unroll
                for (int kf = 0; kf < 4; kf++) {
                    uint2 bb = *(const uint2*)(Vb + (hf * 4 + kf) * 512 + (nj * 8 + g) * 8 + tg * 2);
                    mma_tf32(o[0][nj], pa[0][kf][0], pa[0][kf][1], pa[0][kf][2], pa[0][kf][3], bb.x, bb.y);
                    mma_tf32(o[1][nj], pa[1][kf][0], pa[1][kf][1], pa[1][kf][2], pa[1][kf][3], bb.x, bb.y);
                }
            }
        }
    }

    // reduce row sums across quad, normalize, store pair-interleaved
#pragma unroll
    for (int r = 0; r < 4; r++) {
        lp[r] += __shfl_xor_sync(0xffffffffu, lp[r], 1);
        lp[r] += __shfl_xor_sync(0xffffffffu, lp[r], 2);
        lp[r] = 1.0f / lp[r];
    }
#pragma unroll
    for (int mi = 0; mi < 2; mi++) {
        int row = qBase + wid * 32 + mi * 16 + g;
        size_t base = (size_t)(b * SS + row) * HH;
#pragma unroll
        for (int nj = 0; nj < 8; nj++) {
            int cg = h * HDIM + nj * 8 + 2 * tg;
            outp[base + perm8(cg)]                      = f2tf(o[mi][nj][0] * lp[mi * 2]);
            outp[base + perm8(cg + 1)]                  = f2tf(o[mi][nj][1] * lp[mi * 2]);
            outp[base + (size_t)8 * HH + perm8(cg)]     = f2tf(o[mi][nj][2] * lp[mi * 2 + 1]);
            outp[base + (size_t)8 * HH + perm8(cg + 1)] = f2tf(o[mi][nj][3] * lp[mi * 2 + 1]);
        }
    }
}

// ---------------------------------------------------------------------------
extern "C" void kernel_launch(void* const* d_in, const int* in_sizes, int n_in,
                              void* d_out, int out_size)
{
    const float* X  = (const float*)d_in[0];
    const float* Wq = (const float*)d_in[1];
    const float* bq = (const float*)d_in[2];
    const float* Wk = (const float*)d_in[3];
    const float* bk = (const float*)d_in[4];
    const float* Wv = (const float*)d_in[5];
    const float* bv = (const float*)d_in[6];
    const float* Wo = (const float*)d_in[7];
    const float* bo = (const float*)d_in[8];
    float* out = (float*)d_out;

    unsigned *xp, *wqkv, *wo, *q, *k, *v, *at;
    cudaGetSymbolAddress((void**)&xp,   g_xp);
    cudaGetSymbolAddress((void**)&wqkv, g_wqkv);
    cudaGetSymbolAddress((void**)&wo,   g_wo);
    cudaGetSymbolAddress((void**)&q,    g_q);
    cudaGetSymbolAddress((void**)&k,    g_k);
    cudaGetSymbolAddress((void**)&v,    g_v);
    cudaGetSymbolAddress((void**)&at,   g_at);

    const int smA  = (2 * 256 * 40 + 2 * 4 * 128 * 8) * 4;   // 114688
    const int smAt = (2 * 64 * 72 + 2 * 4096) * 4;           // 69632

    cudaFuncSetAttribute(gemm_db<0>, cudaFuncAttributeMaxDynamicSharedMemorySize, smA);
    cudaFuncSetAttribute(gemm_db<5>, cudaFuncAttributeMaxDynamicSharedMemorySize, smA);
    cudaFuncSetAttribute(mqa_attn_tc9, cudaFuncAttributeMaxDynamicSharedMemorySize, smAt);
    cudaFuncSetAttribute(mqa_attn_tc9, cudaFuncAttributePreferredSharedMemoryCarveout, 100);

    const float qscale = 0.125f * 1.44269504088896340736f;  // 1/sqrt(64) * log2(e)

    // launch 1: X convert
    cvt_x_sh<<<(MM * HH / 4 + 255) / 256, 256>>>((const float4*)X, (uint4*)xp, MM * HH / 4);
    // launch 2: all weight converts
    const int nw = 2 * HH * HH + HH * 128;
    cvt_w_all<<<(nw + 255) / 256, 256>>>(Wq, Wk, Wv, Wo, wqkv, wo);
    // launch 3: fused QKV projection
    gemm_db<5><<<dim3(NQKV / 128, MM / 256), 256, smA>>>(
        xp, wqkv, bq, bk, bv, q, k, v, MM, NQKV, HH, qscale);
    // launch 4 (ncu window): attention
    mqa_attn_tc9<<<dim3(SS / 128, NHEAD, BB), 128, smAt>>>(q, k, v, at);
    // launch 5: output projection
    gemm_db<0><<<dim3(HH / 128, MM / 256), 256, smA>>>(
        at, wo, bo, nullptr, nullptr, out, nullptr, nullptr, MM, HH, HH, 1.0f);
}

// round 13
// speedup vs baseline: 1.7830x; 1.0244x over previous
#include <cuda_runtime.h>
#include <math.h>

#define BB 4
#define SS 2048
#define HH 1024
#define NHEAD 16
#define HDIM 64
#define MM (BB * SS)   // 8192
#define NQKV 1152      // 1024 (Q) + 64 (K) + 64 (V)

// ---------------------------------------------------------------------------
// scratch (__device__ globals; allocation-free)
// ---------------------------------------------------------------------------
__device__ unsigned g_xp[MM * HH];         // X, tf32, pair-interleaved cols
__device__ unsigned g_wqkv[HH * NQKV];     // Wq|Wk|Wv packed, kperm layout
__device__ unsigned g_wo[HH * HH];         // Wo, kperm layout
__device__ unsigned g_q [MM * HH];         // Q, tf32, pre-scaled 0.125*log2e (plain)
__device__ unsigned g_k [MM * HDIM];       // K, tf32, pair-interleaved cols
__device__ unsigned g_v [MM * HDIM];       // V, tf32, natural [s/8][d][8]
__device__ unsigned g_at[MM * HH];         // attn out, tf32, pair-interleaved

// ---------------------------------------------------------------------------
// helpers
// ---------------------------------------------------------------------------
__device__ __forceinline__ unsigned f2tf(float f) {
    unsigned u;
    asm("cvt.rna.tf32.f32 %0, %1;" : "=r"(u) : "f"(f));
    return u;
}
__device__ __forceinline__ float ex2(float f) {
    float r;
    asm("ex2.approx.f32 %0, %1;" : "=f"(r) : "f"(f));
    return r;
}
__device__ __forceinline__ int perm8(int c) {
    return (c & ~7) | ((c & 3) << 1) | ((c >> 2) & 1);
}
__device__ __forceinline__ size_t kperm(int k, int n, int N) {
    return (size_t)(k >> 3) * N * 8 + n * 8 + (k & 3) * 2 + ((k >> 2) & 1);
}
// natural V layout: key s, dim d -> word (s/8)*512 + d*8 + (s%8)
__device__ __forceinline__ size_t vnat(int s, int d) {
    return (size_t)(s >> 3) * (HDIM * 8) + d * 8 + (s & 7);
}
__device__ __forceinline__ void mma_tf32(float c[4],
                                         unsigned a0, unsigned a1,
                                         unsigned a2, unsigned a3,
                                         unsigned b0, unsigned b1) {
    asm volatile(
        "mma.sync.aligned.m16n8k8.row.col.f32.tf32.tf32.f32 "
        "{%0,%1,%2,%3}, {%4,%5,%6,%7}, {%8,%9}, {%0,%1,%2,%3};"
        : "+f"(c[0]), "+f"(c[1]), "+f"(c[2]), "+f"(c[3])
        : "r"(a0), "r"(a1), "r"(a2), "r"(a3), "r"(b0), "r"(b1));
}
__device__ __forceinline__ void cpa16(unsigned* smem_dst, const unsigned* gmem_src) {
    unsigned s = (unsigned)__cvta_generic_to_shared(smem_dst);
    asm volatile("cp.async.cg.shared.global [%0], [%1], 16;" :: "r"(s), "l"(gmem_src));
}
#define CP_COMMIT() asm volatile("cp.async.commit_group;")
#define CP_WAIT0()  asm volatile("cp.async.wait_group 0;")

// ---------------------------------------------------------------------------
// pre-convert kernels (2 launches)
// ---------------------------------------------------------------------------
__global__ void cvt_x_sh(const float4* __restrict__ in, uint4* __restrict__ out, int n4) {
    int idx = blockIdx.x * 256 + threadIdx.x;
    if (idx < n4) {
        float4 v = in[idx];
        unsigned x0 = f2tf(v.x), x1 = f2tf(v.y), x2 = f2tf(v.z), x3 = f2tf(v.w);
        bool odd = threadIdx.x & 1;
        unsigned a = odd ? x0 : x2;
        unsigned b = odd ? x1 : x3;
        unsigned sa = __shfl_xor_sync(0xffffffffu, a, 1);
        unsigned sb = __shfl_xor_sync(0xffffffffu, b, 1);
        uint4 o;
        if (!odd) { o.x = x0; o.y = sa; o.z = x1; o.w = sb; }
        else      { o.x = sa; o.y = x2; o.z = sb; o.w = x3; }
        out[idx] = o;
    }
}
__global__ void cvt_w_all(const float* __restrict__ Wq, const float* __restrict__ Wk,
                          const float* __restrict__ Wv, const float* __restrict__ Wo,
                          unsigned* __restrict__ wqkv, unsigned* __restrict__ wo)
{
    int i = blockIdx.x * 256 + threadIdx.x;
    if (i < HH * HH) {
        int nn = i & (HH - 1), k = i >> 10;
        wqkv[kperm(k, nn, NQKV)] = f2tf(Wq[i]);
    } else if (i < HH * HH + HH * 128) {
        int j = i - HH * HH;
        int nn = j & 127, k = j >> 7;
        float v = (nn < HDIM) ? Wk[k * HDIM + nn] : Wv[k * HDIM + nn - HDIM];
        wqkv[kperm(k, HH + nn, NQKV)] = f2tf(v);
    } else if (i < 2 * HH * HH + HH * 128) {
        int j = i - HH * HH - HH * 128;
        int nn = j & (HH - 1), k = j >> 10;
        wo[kperm(k, nn, HH)] = f2tf(Wo[j]);
    }
}

// ---------------------------------------------------------------------------
// double-buffered tf32 GEMM v3: 128-thread CTAs, 2 CTAs/SM.
// A: pair-interleaved cols [M][K]. W: kperm [K/8][N][8].
// BM=128, BN=128, BK=32, 4 warps (2x2 of 64x64 warp tiles), acc=128 regs.
// smem 72KB/CTA -> 2 CTAs co-resident. Per-output k-summation order is
// identical to the previous GEMM (same BK/ks/MMA sequence).
// MODE 0: fp32+bias -> final out. MODE 5: QKV routing epilogue.
// ---------------------------------------------------------------------------
template <int MODE>
__global__ __launch_bounds__(128, 2) void gemm_db(
    const unsigned* __restrict__ A, const unsigned* __restrict__ W,
    const float* __restrict__ bias, const float* __restrict__ bias2,
    const float* __restrict__ bias3,
    void* __restrict__ Cout, void* __restrict__ Cout2, void* __restrict__ Cout3,
    int M, int N, int K, float oscale)
{
    constexpr int BM = 128, BN = 128, BK = 32;
    constexpr int NTHR = 128;
    constexpr int AST = 40;
    constexpr int BWORDS = 4 * BN * 8;     // 4096 words

    extern __shared__ unsigned sm[];
    unsigned* As = sm;                     // [2][BM][AST]
    unsigned* Bs = sm + 2 * BM * AST;      // [2][4][BN*8]

    const int tid = threadIdx.x;
    const int wid = tid >> 5, lane = tid & 31, g = lane >> 2, tg = lane & 3;
    const int wm = (wid & 1) * 64;
    const int wn = (wid >> 1) * 64;
    const int rowBase = blockIdx.y * BM, colBase = blockIdx.x * BN;

    float acc[4][8][4];
#pragma unroll
    for (int mi = 0; mi < 4; mi++)
#pragma unroll
        for (int nj = 0; nj < 8; nj++)
#pragma unroll
            for (int r = 0; r < 4; r++) acc[mi][nj][r] = 0.0f;

    auto issue = [&](int kt, int buf) {
        const unsigned* Ag = A + (size_t)rowBase * K + kt;
        unsigned* Ab = As + buf * BM * AST;
#pragma unroll
        for (int i = 0; i < (BM * BK / 4) / NTHR; i++) {   // 8
            int ch = tid + i * NTHR;
            int r = ch >> 3, cw = ch & 7;
            cpa16(Ab + r * AST + cw * 4, Ag + (size_t)r * K + cw * 4);
        }
        const unsigned* Wg = W + (size_t)(kt >> 3) * N * 8 + (size_t)colBase * 8;
        unsigned* Bb = Bs + buf * BWORDS;
#pragma unroll
        for (int i = 0; i < (BWORDS / 4) / NTHR; i++) {    // 8
            int ch = tid + i * NTHR;
            int r = ch >> 8, cw = ch & 255;
            cpa16(Bb + r * BN * 8 + cw * 4, Wg + (size_t)r * N * 8 + cw * 4);
        }
    };

    issue(0, 0);
    CP_COMMIT();

    const int T = K / BK;
    for (int t = 0; t < T; t++) {
        CP_WAIT0();
        __syncthreads();
        if (t + 1 < T) {
            issue((t + 1) * BK, (t + 1) & 1);
            CP_COMMIT();
        }

        const unsigned* Ab = As + (t & 1) * BM * AST;
        const unsigned* Bb = Bs + (t & 1) * BWORDS;
#pragma unroll
        for (int ks = 0; ks < 4; ks++) {
            unsigned a[4][4];
#pragma unroll
            for (int mi = 0; mi < 4; mi++) {
                int row = wm + mi * 16 + g;
                uint2 lo = *(const uint2*)(Ab + row * AST + ks * 8 + tg * 2);
                uint2 hi = *(const uint2*)(Ab + (row + 8) * AST + ks * 8 + tg * 2);
                a[mi][0] = lo.x; a[mi][2] = lo.y;
                a[mi][1] = hi.x; a[mi][3] = hi.y;
            }
#pragma unroll
            for (int nj = 0; nj < 8; nj++) {
                uint2 bb = *(const uint2*)(Bb + ks * BN * 8 + (wn + nj * 8 + g) * 8 + tg * 2);
#pragma unroll
                for (int mi = 0; mi < 4; mi++)
                    mma_tf32(acc[mi][nj], a[mi][0], a[mi][1], a[mi][2], a[mi][3], bb.x, bb.y);
            }
        }
    }

    // epilogue
#pragma unroll
    for (int nj = 0; nj < 8; nj++) {
        int col = colBase + wn + nj * 8 + 2 * tg;
        float bx, by;
        if (MODE == 5) {
            if (col < HH)            { bx = bias[col];        by = bias[col + 1]; }
            else if (col < HH + 64)  { bx = bias2[col - HH];  by = bias2[col - HH + 1]; }
            else                     { bx = bias3[col - HH - 64]; by = bias3[col - HH - 63]; }
        } else {
            bx = bias[col]; by = bias[col + 1];
        }
#pragma unroll
        for (int mi = 0; mi < 4; mi++) {
            int row = rowBase + wm + mi * 16 + g;
            float v00 = acc[mi][nj][0] + bx, v01 = acc[mi][nj][1] + by;
            float v10 = acc[mi][nj][2] + bx, v11 = acc[mi][nj][3] + by;
            if (MODE == 0) {
                float* o = (float*)Cout;
                *(float2*)(o + (size_t)row * N + col) = make_float2(v00, v01);
                *(float2*)(o + (size_t)(row + 8) * N + col) = make_float2(v10, v11);
            } else {
                if (col < HH) {
                    unsigned* o = (unsigned*)Cout;
                    *(uint2*)(o + (size_t)row * HH + col) =
                        make_uint2(f2tf(v00 * oscale), f2tf(v01 * oscale));
                    *(uint2*)(o + (size_t)(row + 8) * HH + col) =
                        make_uint2(f2tf(v10 * oscale), f2tf(v11 * oscale));
                } else if (col < HH + 64) {
                    unsigned* o = (unsigned*)Cout2;
                    int d = col - HH;
                    o[(size_t)row * HDIM + perm8(d)]           = f2tf(v00);
                    o[(size_t)row * HDIM + perm8(d + 1)]       = f2tf(v01);
                    o[(size_t)(row + 8) * HDIM + perm8(d)]     = f2tf(v10);
                    o[(size_t)(row + 8) * HDIM + perm8(d + 1)] = f2tf(v11);
                } else {
                    unsigned* o = (unsigned*)Cout3;
                    int d = col - HH - 64;
                    o[vnat(row, d)]         = f2tf(v00);
                    o[vnat(row, d + 1)]     = f2tf(v01);
                    o[vnat(row + 8, d)]     = f2tf(v10);
                    o[vnat(row + 8, d + 1)] = f2tf(v11);
                }
            }
        }
    }
}

// ---------------------------------------------------------------------------
// MQA flash attention v9 (round-12 winner, unchanged): 128-thread CTAs,
// 2 m-frags/warp, Q register-resident, S C-frag -> PV A-frag direct,
// V natural key order, no online max. grid = (S/128, NH, B).
// ---------------------------------------------------------------------------
__global__ __launch_bounds__(128, 2) void mqa_attn_tc9(
    const unsigned* __restrict__ qp, const unsigned* __restrict__ kp,
    const unsigned* __restrict__ vp, unsigned* __restrict__ outp)
{
    extern __shared__ unsigned sm[];
    unsigned* Ks = sm;                    // [2][64][72]
    unsigned* Vs = sm + 2 * 64 * 72;      // [2][4096]

    const int b = blockIdx.z, h = blockIdx.y;
    const int qBase = blockIdx.x * 128;
    const int tid = threadIdx.x, wid = tid >> 5, lane = tid & 31;
    const int g = lane >> 2, tg = lane & 3;

    unsigned qa[2][8][4];
#pragma unroll
    for (int mi = 0; mi < 2; mi++) {
        int row = qBase + wid * 32 + mi * 16 + g;
        const unsigned* q0 = qp + (size_t)(b * SS + row) * HH + h * HDIM;
#pragma unroll
        for (int kf = 0; kf < 8; kf++) {
            int col = kf * 8 + tg;
            qa[mi][kf][0] = __ldg(q0 + col);
            qa[mi][kf][1] = __ldg(q0 + (size_t)8 * HH + col);
            qa[mi][kf][2] = __ldg(q0 + col + 4);
            qa[mi][kf][3] = __ldg(q0 + (size_t)8 * HH + col + 4);
        }
    }

    float o[2][8][4];
#pragma unroll
    for (int mi = 0; mi < 2; mi++)
#pragma unroll
        for (int nj = 0; nj < 8; nj++)
#pragma unroll
            for (int r = 0; r < 4; r++) o[mi][nj][r] = 0.0f;
    float lp[4] = {0.0f, 0.0f, 0.0f, 0.0f};

    auto issue = [&](int t, int buf) {
        const unsigned* kg = kp + (size_t)(b * SS + t * 64) * HDIM;
        unsigned* kb = Ks + buf * 64 * 72;
#pragma unroll
        for (int i = 0; i < 8; i++) {
            int ch = tid + i * 128;
            int r = ch >> 4, cw = ch & 15;
            cpa16(kb + r * 72 + cw * 4, kg + r * 64 + cw * 4);
        }
        const unsigned* vg = vp + (size_t)(b * SS + t * 64) * HDIM;
        unsigned* vb = Vs + buf * 4096;
#pragma unroll
        for (int i = 0; i < 8; i++) {
            int ch = tid + i * 128;
            cpa16(vb + ch * 4, vg + ch * 4);
        }
    };

    issue(0, 0);
    CP_COMMIT();

    const int T = SS / 64;
    for (int t = 0; t < T; t++) {
        CP_WAIT0();
        __syncthreads();
        if (t + 1 < T) {
            issue(t + 1, (t + 1) & 1);
            CP_COMMIT();
        }

        const unsigned* Kb = Ks + (t & 1) * 64 * 72;
        const unsigned* Vb = Vs + (t & 1) * 4096;

#pragma unroll
        for (int hf = 0; hf < 2; hf++) {
            float s[2][4][4];
#pragma unroll
            for (int mi = 0; mi < 2; mi++)
#pragma unroll
                for (int nj = 0; nj < 4; nj++)
#pragma unroll
                    for (int r = 0; r < 4; r++) s[mi][nj][r] = 0.0f;
#pragma unroll
            for (int kf = 0; kf < 8; kf++) {
#pragma unroll
                for (int nj = 0; nj < 4; nj++) {
                    uint2 bb = *(const uint2*)(Kb + (hf * 32 + nj * 8 + g) * 72 + kf * 8 + tg * 2);
                    mma_tf32(s[0][nj], qa[0][kf][0], qa[0][kf][1], qa[0][kf][2], qa[0][kf][3], bb.x, bb.y);
                    mma_tf32(s[1][nj], qa[1][kf][0], qa[1][kf][1], qa[1][kf][2], qa[1][kf][3], bb.x, bb.y);
                }
            }

            unsigned pa[2][4][4];
#pragma unroll
            for (int mi = 0; mi < 2; mi++)
#pragma unroll
                for (int nj = 0; nj < 4; nj++) {
                    float p0 = ex2(s[mi][nj][0]);
                    float p1 = ex2(s[mi][nj][1]);
                    float p2 = ex2(s[mi][nj][2]);
                    float p3 = ex2(s[mi][nj][3]);
                    lp[mi * 2 + 0] += p0 + p1;
                    lp[mi * 2 + 1] += p2 + p3;
                    pa[mi][nj][0] = f2tf(p0);
                    pa[mi][nj][1] = f2tf(p2);
                    pa[mi][nj][2] = f2tf(p1);
                    pa[mi][nj][3] = f2tf(p3);
                }

#pragma unroll
            for (int nj = 0; nj < 8; nj++) {
#pragma unroll
                for (int kf = 0; kf < 4; kf++) {
                    uint2 bb = *(const uint2*)(Vb + (hf * 4 + kf) * 512 + (nj * 8 + g) * 8 + tg * 2);
                    mma_tf32(o[0][nj], pa[0][kf][0], pa[0][kf][1], pa[0][kf][2], pa[0][kf][3], bb.x, bb.y);
                    mma_tf32(o[1][nj], pa[1][kf][0], pa[1][kf][1], pa[1][kf][2], pa[1][kf][3], bb.x, bb.y);
                }
            }
        }
    }

#pragma unroll
    for (int r = 0; r < 4; r++) {
        lp[r] += __shfl_xor_sync(0xffffffffu, lp[r], 1);
        lp[r] += __shfl_xor_sync(0xffffffffu, lp[r], 2);
        lp[r] = 1.0f / lp[r];
    }
#pragma unroll
    for (int mi = 0; mi < 2; mi++) {
        int row = qBase + wid * 32 + mi * 16 + g;
        size_t base = (size_t)(b * SS + row) * HH;
#pragma unroll
        for (int nj = 0; nj < 8; nj++) {
            int cg = h * HDIM + nj * 8 + 2 * tg;
            outp[base + perm8(cg)]                      = f2tf(o[mi][nj][0] * lp[mi * 2]);
            outp[base + perm8(cg + 1)]                  = f2tf(o[mi][nj][1] * lp[mi * 2]);
            outp[base + (size_t)8 * HH + perm8(cg)]     = f2tf(o[mi][nj][2] * lp[mi * 2 + 1]);
            outp[base + (size_t)8 * HH + perm8(cg + 1)] = f2tf(o[mi][nj][3] * lp[mi * 2 + 1]);
        }
    }
}

// ---------------------------------------------------------------------------
extern "C" void kernel_launch(void* const* d_in, const int* in_sizes, int n_in,
                              void* d_out, int out_size)
{
    const float* X  = (const float*)d_in[0];
    const float* Wq = (const float*)d_in[1];
    const float* bq = (const float*)d_in[2];
    const float* Wk = (const float*)d_in[3];
    const float* bk = (const float*)d_in[4];
    const float* Wv = (const float*)d_in[5];
    const float* bv = (const float*)d_in[6];
    const float* Wo = (const float*)d_in[7];
    const float* bo = (const float*)d_in[8];
    float* out = (float*)d_out;

    unsigned *xp, *wqkv, *wo, *q, *k, *v, *at;
    cudaGetSymbolAddress((void**)&xp,   g_xp);
    cudaGetSymbolAddress((void**)&wqkv, g_wqkv);
    cudaGetSymbolAddress((void**)&wo,   g_wo);
    cudaGetSymbolAddress((void**)&q,    g_q);
    cudaGetSymbolAddress((void**)&k,    g_k);
    cudaGetSymbolAddress((void**)&v,    g_v);
    cudaGetSymbolAddress((void**)&at,   g_at);

    const int smA  = (2 * 128 * 40 + 2 * 4 * 128 * 8) * 4;   // 73728 (2 CTAs/SM)
    const int smAt = (2 * 64 * 72 + 2 * 4096) * 4;           // 69632

    cudaFuncSetAttribute(gemm_db<0>, cudaFuncAttributeMaxDynamicSharedMemorySize, smA);
    cudaFuncSetAttribute(gemm_db<5>, cudaFuncAttributeMaxDynamicSharedMemorySize, smA);
    cudaFuncSetAttribute(gemm_db<0>, cudaFuncAttributePreferredSharedMemoryCarveout, 100);
    cudaFuncSetAttribute(gemm_db<5>, cudaFuncAttributePreferredSharedMemoryCarveout, 100);
    cudaFuncSetAttribute(mqa_attn_tc9, cudaFuncAttributeMaxDynamicSharedMemorySize, smAt);
    cudaFuncSetAttribute(mqa_attn_tc9, cudaFuncAttributePreferredSharedMemoryCarveout, 100);

    const float qscale = 0.125f * 1.44269504088896340736f;  // 1/sqrt(64) * log2(e)

    // launch 1: X convert
    cvt_x_sh<<<(MM * HH / 4 + 255) / 256, 256>>>((const float4*)X, (uint4*)xp, MM * HH / 4);
    // launch 2: all weight converts
    const int nw = 2 * HH * HH + HH * 128;
    cvt_w_all<<<(nw + 255) / 256, 256>>>(Wq, Wk, Wv, Wo, wqkv, wo);
    // launch 3: fused QKV projection (128-thr CTAs, 2/SM)
    gemm_db<5><<<dim3(NQKV / 128, MM / 128), 128, smA>>>(
        xp, wqkv, bq, bk, bv, q, k, v, MM, NQKV, HH, qscale);
    // launch 4 (ncu window): attention
    mqa_attn_tc9<<<dim3(SS / 128, NHEAD, BB), 128, smAt>>>(q, k, v, at);
    // launch 5: output projection
    gemm_db<0><<<dim3(HH / 128, MM / 128), 128, smA>>>(
        at, wo, bo, nullptr, nullptr, out, nullptr, nullptr, MM, HH, HH, 1.0f);
}

// round 14
// speedup vs baseline: 1.8037x; 1.0116x over previous
#include <cuda_runtime.h>
#include <math.h>

#define BB 4
#define SS 2048
#define HH 1024
#define NHEAD 16
#define HDIM 64
#define MM (BB * SS)   // 8192
#define NQKV 1152      // 1024 (Q) + 64 (K) + 64 (V)

// ---------------------------------------------------------------------------
// scratch (__device__ globals; allocation-free)
// ---------------------------------------------------------------------------
__device__ unsigned g_xp[MM * HH];         // X, tf32, pair-interleaved cols
__device__ unsigned g_wqkv[HH * NQKV];     // Wq|Wk|Wv packed, kperm layout
__device__ unsigned g_wo[HH * HH];         // Wo, kperm layout
__device__ unsigned g_q [MM * HH];         // Q, tf32, pre-scaled 0.125*log2e (plain)
__device__ unsigned g_k [MM * HDIM];       // K, tf32, pair-interleaved cols
__device__ unsigned g_v [MM * HDIM];       // V, tf32, natural [s/8][d][8]
__device__ unsigned g_at[MM * HH];         // attn out, tf32, pair-interleaved

// ---------------------------------------------------------------------------
// helpers
// ---------------------------------------------------------------------------
__device__ __forceinline__ unsigned f2tf(float f) {
    unsigned u;
    asm("cvt.rna.tf32.f32 %0, %1;" : "=r"(u) : "f"(f));
    return u;
}
__device__ __forceinline__ float ex2(float f) {
    float r;
    asm("ex2.approx.f32 %0, %1;" : "=f"(r) : "f"(f));
    return r;
}
__device__ __forceinline__ int perm8(int c) {
    return (c & ~7) | ((c & 3) << 1) | ((c >> 2) & 1);
}
__device__ __forceinline__ size_t kperm(int k, int n, int N) {
    return (size_t)(k >> 3) * N * 8 + n * 8 + (k & 3) * 2 + ((k >> 2) & 1);
}
// natural V layout: key s, dim d -> word (s/8)*512 + d*8 + (s%8)
__device__ __forceinline__ size_t vnat(int s, int d) {
    return (size_t)(s >> 3) * (HDIM * 8) + d * 8 + (s & 7);
}
__device__ __forceinline__ void mma_tf32(float c[4],
                                         unsigned a0, unsigned a1,
                                         unsigned a2, unsigned a3,
                                         unsigned b0, unsigned b1) {
    asm volatile(
        "mma.sync.aligned.m16n8k8.row.col.f32.tf32.tf32.f32 "
        "{%0,%1,%2,%3}, {%4,%5,%6,%7}, {%8,%9}, {%0,%1,%2,%3};"
        : "+f"(c[0]), "+f"(c[1]), "+f"(c[2]), "+f"(c[3])
        : "r"(a0), "r"(a1), "r"(a2), "r"(a3), "r"(b0), "r"(b1));
}
__device__ __forceinline__ void cpa16(unsigned* smem_dst, const unsigned* gmem_src) {
    unsigned s = (unsigned)__cvta_generic_to_shared(smem_dst);
    asm volatile("cp.async.cg.shared.global [%0], [%1], 16;" :: "r"(s), "l"(gmem_src));
}
#define CP_COMMIT() asm volatile("cp.async.commit_group;")
#define CP_WAIT0()  asm volatile("cp.async.wait_group 0;")

// ---------------------------------------------------------------------------
// pre-convert kernels (2 launches)
// ---------------------------------------------------------------------------
__global__ void cvt_x_sh(const float4* __restrict__ in, uint4* __restrict__ out, int n4) {
    int idx = blockIdx.x * 256 + threadIdx.x;
    if (idx < n4) {
        float4 v = in[idx];
        unsigned x0 = f2tf(v.x), x1 = f2tf(v.y), x2 = f2tf(v.z), x3 = f2tf(v.w);
        bool odd = threadIdx.x & 1;
        unsigned a = odd ? x0 : x2;
        unsigned b = odd ? x1 : x3;
        unsigned sa = __shfl_xor_sync(0xffffffffu, a, 1);
        unsigned sb = __shfl_xor_sync(0xffffffffu, b, 1);
        uint4 o;
        if (!odd) { o.x = x0; o.y = sa; o.z = x1; o.w = sb; }
        else      { o.x = sa; o.y = x2; o.z = sb; o.w = x3; }
        out[idx] = o;
    }
}
__global__ void cvt_w_all(const float* __restrict__ Wq, const float* __restrict__ Wk,
                          const float* __restrict__ Wv, const float* __restrict__ Wo,
                          unsigned* __restrict__ wqkv, unsigned* __restrict__ wo)
{
    int i = blockIdx.x * 256 + threadIdx.x;
    if (i < HH * HH) {
        int nn = i & (HH - 1), k = i >> 10;
        wqkv[kperm(k, nn, NQKV)] = f2tf(Wq[i]);
    } else if (i < HH * HH + HH * 128) {
        int j = i - HH * HH;
        int nn = j & 127, k = j >> 7;
        float v = (nn < HDIM) ? Wk[k * HDIM + nn] : Wv[k * HDIM + nn - HDIM];
        wqkv[kperm(k, HH + nn, NQKV)] = f2tf(v);
    } else if (i < 2 * HH * HH + HH * 128) {
        int j = i - HH * HH - HH * 128;
        int nn = j & (HH - 1), k = j >> 10;
        wo[kperm(k, nn, HH)] = f2tf(Wo[j]);
    }
}

// ---------------------------------------------------------------------------
// double-buffered tf32 GEMM v4: 128-thread CTAs, 2 CTAs/SM, PLUS explicit
// register double-buffering of A/B fragments across ks steps (LDS for ks+1
// issued before the MMAs of ks -> LDS latency hidden in-schedule).
// A: pair-interleaved cols [M][K]. W: kperm [K/8][N][8].
// BM=128, BN=128, BK=32, 4 warps (2x2 of 64x64 warp tiles).
// MODE 0: fp32+bias -> final out. MODE 5: QKV routing epilogue.
// ---------------------------------------------------------------------------
template <int MODE>
__global__ __launch_bounds__(128, 2) void gemm_db(
    const unsigned* __restrict__ A, const unsigned* __restrict__ W,
    const float* __restrict__ bias, const float* __restrict__ bias2,
    const float* __restrict__ bias3,
    void* __restrict__ Cout, void* __restrict__ Cout2, void* __restrict__ Cout3,
    int M, int N, int K, float oscale)
{
    constexpr int BM = 128, BN = 128, BK = 32;
    constexpr int NTHR = 128;
    constexpr int AST = 40;
    constexpr int BWORDS = 4 * BN * 8;     // 4096 words

    extern __shared__ unsigned sm[];
    unsigned* As = sm;                     // [2][BM][AST]
    unsigned* Bs = sm + 2 * BM * AST;      // [2][4][BN*8]

    const int tid = threadIdx.x;
    const int wid = tid >> 5, lane = tid & 31, g = lane >> 2, tg = lane & 3;
    const int wm = (wid & 1) * 64;
    const int wn = (wid >> 1) * 64;
    const int rowBase = blockIdx.y * BM, colBase = blockIdx.x * BN;

    float acc[4][8][4];
#pragma unroll
    for (int mi = 0; mi < 4; mi++)
#pragma unroll
        for (int nj = 0; nj < 8; nj++)
#pragma unroll
            for (int r = 0; r < 4; r++) acc[mi][nj][r] = 0.0f;

    auto issue = [&](int kt, int buf) {
        const unsigned* Ag = A + (size_t)rowBase * K + kt;
        unsigned* Ab = As + buf * BM * AST;
#pragma unroll
        for (int i = 0; i < (BM * BK / 4) / NTHR; i++) {   // 8
            int ch = tid + i * NTHR;
            int r = ch >> 3, cw = ch & 7;
            cpa16(Ab + r * AST + cw * 4, Ag + (size_t)r * K + cw * 4);
        }
        const unsigned* Wg = W + (size_t)(kt >> 3) * N * 8 + (size_t)colBase * 8;
        unsigned* Bb = Bs + buf * BWORDS;
#pragma unroll
        for (int i = 0; i < (BWORDS / 4) / NTHR; i++) {    // 8
            int ch = tid + i * NTHR;
            int r = ch >> 8, cw = ch & 255;
            cpa16(Bb + r * BN * 8 + cw * 4, Wg + (size_t)r * N * 8 + cw * 4);
        }
    };

    issue(0, 0);
    CP_COMMIT();

    const int T = K / BK;
    for (int t = 0; t < T; t++) {
        CP_WAIT0();
        __syncthreads();
        if (t + 1 < T) {
            issue((t + 1) * BK, (t + 1) & 1);
            CP_COMMIT();
        }

        const unsigned* Ab = As + (t & 1) * BM * AST;
        const unsigned* Bb = Bs + (t & 1) * BWORDS;

        // register double-buffered fragments across ks
        uint2 aF[2][8];   // [phase][mi*2 + (0:row, 1:row+8)]
        uint2 bF[2][8];   // [phase][nj]

#pragma unroll
        for (int mi = 0; mi < 4; mi++) {
            int row = wm + mi * 16 + g;
            aF[0][mi * 2]     = *(const uint2*)(Ab + row * AST + tg * 2);
            aF[0][mi * 2 + 1] = *(const uint2*)(Ab + (row + 8) * AST + tg * 2);
        }
#pragma unroll
        for (int nj = 0; nj < 8; nj++)
            bF[0][nj] = *(const uint2*)(Bb + (wn + nj * 8 + g) * 8 + tg * 2);

#pragma unroll
        for (int ks = 0; ks < 4; ks++) {
            int cur = ks & 1, nxt = cur ^ 1;
            if (ks < 3) {
#pragma unroll
                for (int mi = 0; mi < 4; mi++) {
                    int row = wm + mi * 16 + g;
                    aF[nxt][mi * 2]     = *(const uint2*)(Ab + row * AST + (ks + 1) * 8 + tg * 2);
                    aF[nxt][mi * 2 + 1] = *(const uint2*)(Ab + (row + 8) * AST + (ks + 1) * 8 + tg * 2);
                }
#pragma unroll
                for (int nj = 0; nj < 8; nj++)
                    bF[nxt][nj] = *(const uint2*)(Bb + (ks + 1) * BN * 8 + (wn + nj * 8 + g) * 8 + tg * 2);
            }
#pragma unroll
            for (int nj = 0; nj < 8; nj++)
#pragma unroll
                for (int mi = 0; mi < 4; mi++)
                    mma_tf32(acc[mi][nj],
                             aF[cur][mi * 2].x, aF[cur][mi * 2 + 1].x,
                             aF[cur][mi * 2].y, aF[cur][mi * 2 + 1].y,
                             bF[cur][nj].x, bF[cur][nj].y);
        }
    }

    // epilogue
#pragma unroll
    for (int nj = 0; nj < 8; nj++) {
        int col = colBase + wn + nj * 8 + 2 * tg;
        float bx, by;
        if (MODE == 5) {
            if (col < HH)            { bx = bias[col];        by = bias[col + 1]; }
            else if (col < HH + 64)  { bx = bias2[col - HH];  by = bias2[col - HH + 1]; }
            else                     { bx = bias3[col - HH - 64]; by = bias3[col - HH - 63]; }
        } else {
            bx = bias[col]; by = bias[col + 1];
        }
#pragma unroll
        for (int mi = 0; mi < 4; mi++) {
            int row = rowBase + wm + mi * 16 + g;
            float v00 = acc[mi][nj][0] + bx, v01 = acc[mi][nj][1] + by;
            float v10 = acc[mi][nj][2] + bx, v11 = acc[mi][nj][3] + by;
            if (MODE == 0) {
                float* o = (float*)Cout;
                *(float2*)(o + (size_t)row * N + col) = make_float2(v00, v01);
                *(float2*)(o + (size_t)(row + 8) * N + col) = make_float2(v10, v11);
            } else {
                if (col < HH) {
                    unsigned* o = (unsigned*)Cout;
                    *(uint2*)(o + (size_t)row * HH + col) =
                        make_uint2(f2tf(v00 * oscale), f2tf(v01 * oscale));
                    *(uint2*)(o + (size_t)(row + 8) * HH + col) =
                        make_uint2(f2tf(v10 * oscale), f2tf(v11 * oscale));
                } else if (col < HH + 64) {
                    unsigned* o = (unsigned*)Cout2;
                    int d = col - HH;
                    o[(size_t)row * HDIM + perm8(d)]           = f2tf(v00);
                    o[(size_t)row * HDIM + perm8(d + 1)]       = f2tf(v01);
                    o[(size_t)(row + 8) * HDIM + perm8(d)]     = f2tf(v10);
                    o[(size_t)(row + 8) * HDIM + perm8(d + 1)] = f2tf(v11);
                } else {
                    unsigned* o = (unsigned*)Cout3;
                    int d = col - HH - 64;
                    o[vnat(row, d)]         = f2tf(v00);
                    o[vnat(row, d + 1)]     = f2tf(v01);
                    o[vnat(row + 8, d)]     = f2tf(v10);
                    o[vnat(row + 8, d + 1)] = f2tf(v11);
                }
            }
        }
    }
}

// ---------------------------------------------------------------------------
// MQA flash attention v9 (round-12 winner, unchanged): 128-thread CTAs,
// 2 m-frags/warp, Q register-resident, S C-frag -> PV A-frag direct,
// V natural key order, no online max. grid = (S/128, NH, B).
// ---------------------------------------------------------------------------
__global__ __launch_bounds__(128, 2) void mqa_attn_tc9(
    const unsigned* __restrict__ qp, const unsigned* __restrict__ kp,
    const unsigned* __restrict__ vp, unsigned* __restrict__ outp)
{
    extern __shared__ unsigned sm[];
    unsigned* Ks = sm;                    // [2][64][72]
    unsigned* Vs = sm + 2 * 64 * 72;      // [2][4096]

    const int b = blockIdx.z, h = blockIdx.y;
    const int qBase = blockIdx.x * 128;
    const int tid = threadIdx.x, wid = tid >> 5, lane = tid & 31;
    const int g = lane >> 2, tg = lane & 3;

    unsigned qa[2][8][4];
#pragma unroll
    for (int mi = 0; mi < 2; mi++) {
        int row = qBase + wid * 32 + mi * 16 + g;
        const unsigned* q0 = qp + (size_t)(b * SS + row) * HH + h * HDIM;
#pragma unroll
        for (int kf = 0; kf < 8; kf++) {
            int col = kf * 8 + tg;
            qa[mi][kf][0] = __ldg(q0 + col);
            qa[mi][kf][1] = __ldg(q0 + (size_t)8 * HH + col);
            qa[mi][kf][2] = __ldg(q0 + col + 4);
            qa[mi][kf][3] = __ldg(q0 + (size_t)8 * HH + col + 4);
        }
    }

    float o[2][8][4];
#pragma unroll
    for (int mi = 0; mi < 2; mi++)
#pragma unroll
        for (int nj = 0; nj < 8; nj++)
#pragma unroll
            for (int r = 0; r < 4; r++) o[mi][nj][r] = 0.0f;
    float lp[4] = {0.0f, 0.0f, 0.0f, 0.0f};

    auto issue = [&](int t, int buf) {
        const unsigned* kg = kp + (size_t)(b * SS + t * 64) * HDIM;
        unsigned* kb = Ks + buf * 64 * 72;
#pragma unroll
        for (int i = 0; i < 8; i++) {
            int ch = tid + i * 128;
            int r = ch >> 4, cw = ch & 15;
            cpa16(kb + r * 72 + cw * 4, kg + r * 64 + cw * 4);
        }
        const unsigned* vg = vp + (size_t)(b * SS + t * 64) * HDIM;
        unsigned* vb = Vs + buf * 4096;
#pragma unroll
        for (int i = 0; i < 8; i++) {
            int ch = tid + i * 128;
            cpa16(vb + ch * 4, vg + ch * 4);
        }
    };

    issue(0, 0);
    CP_COMMIT();

    const int T = SS / 64;
    for (int t = 0; t < T; t++) {
        CP_WAIT0();
        __syncthreads();
        if (t + 1 < T) {
            issue(t + 1, (t + 1) & 1);
            CP_COMMIT();
        }

        const unsigned* Kb = Ks + (t & 1) * 64 * 72;
        const unsigned* Vb = Vs + (t & 1) * 4096;

#pragma unroll
        for (int hf = 0; hf < 2; hf++) {
            float s[2][4][4];
#pragma unroll
            for (int mi = 0; mi < 2; mi++)
#pragma unroll
                for (int nj = 0; nj < 4; nj++)
#pragma unroll
                    for (int r = 0; r < 4; r++) s[mi][nj][r] = 0.0f;
#pragma unroll
            for (int kf = 0; kf < 8; kf++) {
#pragma unroll
                for (int nj = 0; nj < 4; nj++) {
                    uint2 bb = *(const uint2*)(Kb + (hf * 32 + nj * 8 + g) * 72 + kf * 8 + tg * 2);
                    mma_tf32(s[0][nj], qa[0][kf][0], qa[0][kf][1], qa[0][kf][2], qa[0][kf][3], bb.x, bb.y);
                    mma_tf32(s[1][nj], qa[1][kf][0], qa[1][kf][1], qa[1][kf][2], qa[1][kf][3], bb.x, bb.y);
                }
            }

            unsigned pa[2][4][4];
#pragma unroll
            for (int mi = 0; mi < 2; mi++)
#pragma unroll
                for (int nj = 0; nj < 4; nj++) {
                    float p0 = ex2(s[mi][nj][0]);
                    float p1 = ex2(s[mi][nj][1]);
                    float p2 = ex2(s[mi][nj][2]);
                    float p3 = ex2(s[mi][nj][3]);
                    lp[mi * 2 + 0] += p0 + p1;
                    lp[mi * 2 + 1] += p2 + p3;
                    pa[mi][nj][0] = f2tf(p0);
                    pa[mi][nj][1] = f2tf(p2);
                    pa[mi][nj][2] = f2tf(p1);
                    pa[mi][nj][3] = f2tf(p3);
                }

#pragma unroll
            for (int nj = 0; nj < 8; nj++) {
#pragma unroll
                for (int kf = 0; kf < 4; kf++) {
                    uint2 bb = *(const uint2*)(Vb + (hf * 4 + kf) * 512 + (nj * 8 + g) * 8 + tg * 2);
                    mma_tf32(o[0][nj], pa[0][kf][0], pa[0][kf][1], pa[0][kf][2], pa[0][kf][3], bb.x, bb.y);
                    mma_tf32(o[1][nj], pa[1][kf][0], pa[1][kf][1], pa[1][kf][2], pa[1][kf][3], bb.x, bb.y);
                }
            }
        }
    }

#pragma unroll
    for (int r = 0; r < 4; r++) {
        lp[r] += __shfl_xor_sync(0xffffffffu, lp[r], 1);
        lp[r] += __shfl_xor_sync(0xffffffffu, lp[r], 2);
        lp[r] = 1.0f / lp[r];
    }
#pragma unroll
    for (int mi = 0; mi < 2; mi++) {
        int row = qBase + wid * 32 + mi * 16 + g;
        size_t base = (size_t)(b * SS + row) * HH;
#pragma unroll
        for (int nj = 0; nj < 8; nj++) {
            int cg = h * HDIM + nj * 8 + 2 * tg;
            outp[base + perm8(cg)]                      = f2tf(o[mi][nj][0] * lp[mi * 2]);
            outp[base + perm8(cg + 1)]                  = f2tf(o[mi][nj][1] * lp[mi * 2]);
            outp[base + (size_t)8 * HH + perm8(cg)]     = f2tf(o[mi][nj][2] * lp[mi * 2 + 1]);
            outp[base + (size_t)8 * HH + perm8(cg + 1)] = f2tf(o[mi][nj][3] * lp[mi * 2 + 1]);
        }
    }
}

// ---------------------------------------------------------------------------
extern "C" void kernel_launch(void* const* d_in, const int* in_sizes, int n_in,
                              void* d_out, int out_size)
{
    const float* X  = (const float*)d_in[0];
    const float* Wq = (const float*)d_in[1];
    const float* bq = (const float*)d_in[2];
    const float* Wk = (const float*)d_in[3];
    const float* bk = (const float*)d_in[4];
    const float* Wv = (const float*)d_in[5];
    const float* bv = (const float*)d_in[6];
    const float* Wo = (const float*)d_in[7];
    const float* bo = (const float*)d_in[8];
    float* out = (float*)d_out;

    unsigned *xp, *wqkv, *wo, *q, *k, *v, *at;
    cudaGetSymbolAddress((void**)&xp,   g_xp);
    cudaGetSymbolAddress((void**)&wqkv, g_wqkv);
    cudaGetSymbolAddress((void**)&wo,   g_wo);
    cudaGetSymbolAddress((void**)&q,    g_q);
    cudaGetSymbolAddress((void**)&k,    g_k);
    cudaGetSymbolAddress((void**)&v,    g_v);
    cudaGetSymbolAddress((void**)&at,   g_at);

    const int smA  = (2 * 128 * 40 + 2 * 4 * 128 * 8) * 4;   // 73728 (2 CTAs/SM)
    const int smAt = (2 * 64 * 72 + 2 * 4096) * 4;           // 69632

    cudaFuncSetAttribute(gemm_db<0>, cudaFuncAttributeMaxDynamicSharedMemorySize, smA);
    cudaFuncSetAttribute(gemm_db<5>, cudaFuncAttributeMaxDynamicSharedMemorySize, smA);
    cudaFuncSetAttribute(gemm_db<0>, cudaFuncAttributePreferredSharedMemoryCarveout, 100);
    cudaFuncSetAttribute(gemm_db<5>, cudaFuncAttributePreferredSharedMemoryCarveout, 100);
    cudaFuncSetAttribute(mqa_attn_tc9, cudaFuncAttributeMaxDynamicSharedMemorySize, smAt);
    cudaFuncSetAttribute(mqa_attn_tc9, cudaFuncAttributePreferredSharedMemoryCarveout, 100);

    const float qscale = 0.125f * 1.44269504088896340736f;  // 1/sqrt(64) * log2(e)

    // launch 1: X convert
    cvt_x_sh<<<(MM * HH / 4 + 255) / 256, 256>>>((const float4*)X, (uint4*)xp, MM * HH / 4);
    // launch 2: all weight converts
    const int nw = 2 * HH * HH + HH * 128;
    cvt_w_all<<<(nw + 255) / 256, 256>>>(Wq, Wk, Wv, Wo, wqkv, wo);
    // launch 3: fused QKV projection (128-thr CTAs, 2/SM, reg-pipelined)
    gemm_db<5><<<dim3(NQKV / 128, MM / 128), 128, smA>>>(
        xp, wqkv, bq, bk, bv, q, k, v, MM, NQKV, HH, qscale);
    // launch 4 (ncu window): attention
    mqa_attn_tc9<<<dim3(SS / 128, NHEAD, BB), 128, smAt>>>(q, k, v, at);
    // launch 5: output projection
    gemm_db<0><<<dim3(HH / 128, MM / 128), 128, smA>>>(
        at, wo, bo, nullptr, nullptr, out, nullptr, nullptr, MM, HH, HH, 1.0f);
}

// round 16
// speedup vs baseline: 1.8147x; 1.0061x over previous
#include <cuda_runtime.h>
#include <math.h>

#define BB 4
#define SS 2048
#define HH 1024
#define NHEAD 16
#define HDIM 64
#define MM (BB * SS)   // 8192
#define NQKV 1152      // 1024 (Q) + 64 (K) + 64 (V)

// ---------------------------------------------------------------------------
// scratch (__device__ globals; allocation-free)
// ---------------------------------------------------------------------------
__device__ unsigned g_xp[MM * HH];         // X, tf32, pair-interleaved cols
__device__ unsigned g_wqkv[HH * NQKV];     // Wq|Wk|Wv packed, kperm layout
__device__ unsigned g_wo[HH * HH];         // Wo, kperm layout
__device__ unsigned g_q [MM * HH];         // Q, tf32, pre-scaled 0.125*log2e (plain)
__device__ unsigned g_k [MM * HDIM];       // K, tf32, pair-interleaved cols
__device__ unsigned g_v [MM * HDIM];       // V, tf32, natural [s/8][d][8]
__device__ unsigned g_at[MM * HH];         // attn out, tf32, pair-interleaved

// ---------------------------------------------------------------------------
// helpers
// ---------------------------------------------------------------------------
__device__ __forceinline__ unsigned f2tf(float f) {
    unsigned u;
    asm("cvt.rna.tf32.f32 %0, %1;" : "=r"(u) : "f"(f));
    return u;
}
__device__ __forceinline__ float ex2(float f) {
    float r;
    asm("ex2.approx.f32 %0, %1;" : "=f"(r) : "f"(f));
    return r;
}
__device__ __forceinline__ int perm8(int c) {
    return (c & ~7) | ((c & 3) << 1) | ((c >> 2) & 1);
}
__device__ __forceinline__ size_t kperm(int k, int n, int N) {
    return (size_t)(k >> 3) * N * 8 + n * 8 + (k & 3) * 2 + ((k >> 2) & 1);
}
// natural V layout: key s, dim d -> word (s/8)*512 + d*8 + (s%8)
__device__ __forceinline__ size_t vnat(int s, int d) {
    return (size_t)(s >> 3) * (HDIM * 8) + d * 8 + (s & 7);
}
__device__ __forceinline__ void mma_tf32(float c[4],
                                         unsigned a0, unsigned a1,
                                         unsigned a2, unsigned a3,
                                         unsigned b0, unsigned b1) {
    asm volatile(
        "mma.sync.aligned.m16n8k8.row.col.f32.tf32.tf32.f32 "
        "{%0,%1,%2,%3}, {%4,%5,%6,%7}, {%8,%9}, {%0,%1,%2,%3};"
        : "+f"(c[0]), "+f"(c[1]), "+f"(c[2]), "+f"(c[3])
        : "r"(a0), "r"(a1), "r"(a2), "r"(a3), "r"(b0), "r"(b1));
}
__device__ __forceinline__ void cpa16(unsigned* smem_dst, const unsigned* gmem_src) {
    unsigned s = (unsigned)__cvta_generic_to_shared(smem_dst);
    asm volatile("cp.async.cg.shared.global [%0], [%1], 16;" :: "r"(s), "l"(gmem_src));
}
#define CP_COMMIT() asm volatile("cp.async.commit_group;")
#define CP_WAIT0()  asm volatile("cp.async.wait_group 0;")

// ---------------------------------------------------------------------------
// single fused pre-convert kernel: X (vectorized, lane-pair shuffle for the
// pair-interleave) then all weights (scatter to kperm layouts).
// ---------------------------------------------------------------------------
#define NX4 (MM * HH / 4)                       // 2,097,152 float4 chunks of X
#define NW  (2 * HH * HH + HH * 128)            // weight elements
__global__ void cvt_fused(const float4* __restrict__ X4,
                          const float* __restrict__ Wq, const float* __restrict__ Wk,
                          const float* __restrict__ Wv, const float* __restrict__ Wo_,
                          uint4* __restrict__ xp4, unsigned* __restrict__ wqkv,
                          unsigned* __restrict__ wo)
{
    int idx = blockIdx.x * 256 + threadIdx.x;
    if (idx < NX4) {
        float4 v = X4[idx];
        unsigned x0 = f2tf(v.x), x1 = f2tf(v.y), x2 = f2tf(v.z), x3 = f2tf(v.w);
        bool odd = threadIdx.x & 1;
        unsigned a = odd ? x0 : x2;
        unsigned b = odd ? x1 : x3;
        unsigned sa = __shfl_xor_sync(0xffffffffu, a, 1);
        unsigned sb = __shfl_xor_sync(0xffffffffu, b, 1);
        uint4 o;
        if (!odd) { o.x = x0; o.y = sa; o.z = x1; o.w = sb; }
        else      { o.x = sa; o.y = x2; o.z = sb; o.w = x3; }
        xp4[idx] = o;
    } else {
        int i = idx - NX4;
        if (i < HH * HH) {
            int nn = i & (HH - 1), k = i >> 10;
            wqkv[kperm(k, nn, NQKV)] = f2tf(Wq[i]);
        } else if (i < HH * HH + HH * 128) {
            int j = i - HH * HH;
            int nn = j & 127, k = j >> 7;
            float v = (nn < HDIM) ? Wk[k * HDIM + nn] : Wv[k * HDIM + nn - HDIM];
            wqkv[kperm(k, HH + nn, NQKV)] = f2tf(v);
        } else if (i < NW) {
            int j = i - HH * HH - HH * 128;
            int nn = j & (HH - 1), k = j >> 10;
            wo[kperm(k, nn, HH)] = f2tf(Wo_[j]);
        }
    }
}

// ---------------------------------------------------------------------------
// double-buffered tf32 GEMM v4 (round-14 winner): 128-thread CTAs, 2 CTAs/SM,
// register double-buffering of A/B fragments across ks steps.
// A: pair-interleaved cols [M][K]. W: kperm [K/8][N][8].
// BM=128, BN=128, BK=32, 4 warps (2x2 of 64x64 warp tiles).
// MODE 0: fp32+bias -> final out. MODE 5: QKV routing epilogue.
// ---------------------------------------------------------------------------
template <int MODE>
__global__ __launch_bounds__(128, 2) void gemm_db(
    const unsigned* __restrict__ A, const unsigned* __restrict__ W,
    const float* __restrict__ bias, const float* __restrict__ bias2,
    const float* __restrict__ bias3,
    void* __restrict__ Cout, void* __restrict__ Cout2, void* __restrict__ Cout3,
    int M, int N, int K, float oscale)
{
    constexpr int BM = 128, BN = 128, BK = 32;
    constexpr int NTHR = 128;
    constexpr int AST = 40;
    constexpr int BWORDS = 4 * BN * 8;     // 4096 words

    extern __shared__ unsigned sm[];
    unsigned* As = sm;                     // [2][BM][AST]
    unsigned* Bs = sm + 2 * BM * AST;      // [2][4][BN*8]

    const int tid = threadIdx.x;
    const int wid = tid >> 5, lane = tid & 31, g = lane >> 2, tg = lane & 3;
    const int wm = (wid & 1) * 64;
    const int wn = (wid >> 1) * 64;
    const int rowBase = blockIdx.y * BM, colBase = blockIdx.x * BN;

    float acc[4][8][4];
#pragma unroll
    for (int mi = 0; mi < 4; mi++)
#pragma unroll
        for (int nj = 0; nj < 8; nj++)
#pragma unroll
            for (int r = 0; r < 4; r++) acc[mi][nj][r] = 0.0f;

    auto issue = [&](int kt, int buf) {
        const unsigned* Ag = A + (size_t)rowBase * K + kt;
        unsigned* Ab = As + buf * BM * AST;
#pragma unroll
        for (int i = 0; i < (BM * BK / 4) / NTHR; i++) {   // 8
            int ch = tid + i * NTHR;
            int r = ch >> 3, cw = ch & 7;
            cpa16(Ab + r * AST + cw * 4, Ag + (size_t)r * K + cw * 4);
        }
        const unsigned* Wg = W + (size_t)(kt >> 3) * N * 8 + (size_t)colBase * 8;
        unsigned* Bb = Bs + buf * BWORDS;
#pragma unroll
        for (int i = 0; i < (BWORDS / 4) / NTHR; i++) {    // 8
            int ch = tid + i * NTHR;
            int r = ch >> 8, cw = ch & 255;
            cpa16(Bb + r * BN * 8 + cw * 4, Wg + (size_t)r * N * 8 + cw * 4);
        }
    };

    issue(0, 0);
    CP_COMMIT();

    const int T = K / BK;
    for (int t = 0; t < T; t++) {
        CP_WAIT0();
        __syncthreads();
        if (t + 1 < T) {
            issue((t + 1) * BK, (t + 1) & 1);
            CP_COMMIT();
        }

        const unsigned* Ab = As + (t & 1) * BM * AST;
        const unsigned* Bb = Bs + (t & 1) * BWORDS;

        uint2 aF[2][8];
        uint2 bF[2][8];

#pragma unroll
        for (int mi = 0; mi < 4; mi++) {
            int row = wm + mi * 16 + g;
            aF[0][mi * 2]     = *(const uint2*)(Ab + row * AST + tg * 2);
            aF[0][mi * 2 + 1] = *(const uint2*)(Ab + (row + 8) * AST + tg * 2);
        }
#pragma unroll
        for (int nj = 0; nj < 8; nj++)
            bF[0][nj] = *(const uint2*)(Bb + (wn + nj * 8 + g) * 8 + tg * 2);

#pragma unroll
        for (int ks = 0; ks < 4; ks++) {
            int cur = ks & 1, nxt = cur ^ 1;
            if (ks < 3) {
#pragma unroll
                for (int mi = 0; mi < 4; mi++) {
                    int row = wm + mi * 16 + g;
                    aF[nxt][mi * 2]     = *(const uint2*)(Ab + row * AST + (ks + 1) * 8 + tg * 2);
                    aF[nxt][mi * 2 + 1] = *(const uint2*)(Ab + (row + 8) * AST + (ks + 1) * 8 + tg * 2);
                }
#pragma unroll
                for (int nj = 0; nj < 8; nj++)
                    bF[nxt][nj] = *(const uint2*)(Bb + (ks + 1) * BN * 8 + (wn + nj * 8 + g) * 8 + tg * 2);
            }
#pragma unroll
            for (int nj = 0; nj < 8; nj++)
#pragma unroll
                for (int mi = 0; mi < 4; mi++)
                    mma_tf32(acc[mi][nj],
                             aF[cur][mi * 2].x, aF[cur][mi * 2 + 1].x,
                             aF[cur][mi * 2].y, aF[cur][mi * 2 + 1].y,
                             bF[cur][nj].x, bF[cur][nj].y);
        }
    }

    // epilogue
#pragma unroll
    for (int nj = 0; nj < 8; nj++) {
        int col = colBase + wn + nj * 8 + 2 * tg;
        float bx, by;
        if (MODE == 5) {
            if (col < HH)            { bx = bias[col];        by = bias[col + 1]; }
            else if (col < HH + 64)  { bx = bias2[col - HH];  by = bias2[col - HH + 1]; }
            else                     { bx = bias3[col - HH - 64]; by = bias3[col - HH - 63]; }
        } else {
            bx = bias[col]; by = bias[col + 1];
        }
#pragma unroll
        for (int mi = 0; mi < 4; mi++) {
            int row = rowBase + wm + mi * 16 + g;
            float v00 = acc[mi][nj][0] + bx, v01 = acc[mi][nj][1] + by;
            float v10 = acc[mi][nj][2] + bx, v11 = acc[mi][nj][3] + by;
            if (MODE == 0) {
                float* o = (float*)Cout;
                *(float2*)(o + (size_t)row * N + col) = make_float2(v00, v01);
                *(float2*)(o + (size_t)(row + 8) * N + col) = make_float2(v10, v11);
            } else {
                if (col < HH) {
                    unsigned* o = (unsigned*)Cout;
                    *(uint2*)(o + (size_t)row * HH + col) =
                        make_uint2(f2tf(v00 * oscale), f2tf(v01 * oscale));
                    *(uint2*)(o + (size_t)(row + 8) * HH + col) =
                        make_uint2(f2tf(v10 * oscale), f2tf(v11 * oscale));
                } else if (col < HH + 64) {
                    unsigned* o = (unsigned*)Cout2;
                    int d = col - HH;
                    o[(size_t)row * HDIM + perm8(d)]           = f2tf(v00);
                    o[(size_t)row * HDIM + perm8(d + 1)]       = f2tf(v01);
                    o[(size_t)(row + 8) * HDIM + perm8(d)]     = f2tf(v10);
                    o[(size_t)(row + 8) * HDIM + perm8(d + 1)] = f2tf(v11);
                } else {
                    unsigned* o = (unsigned*)Cout3;
                    int d = col - HH - 64;
                    o[vnat(row, d)]         = f2tf(v00);
                    o[vnat(row, d + 1)]     = f2tf(v01);
                    o[vnat(row + 8, d)]     = f2tf(v10);
                    o[vnat(row + 8, d + 1)] = f2tf(v11);
                }
            }
        }
    }
}

// ---------------------------------------------------------------------------
// MQA flash attention v9 (round-12/13/14 winner, unchanged): 128-thread CTAs,
// 2 m-frags/warp, Q register-resident, S C-frag -> PV A-frag direct,
// V natural key order, no online max. grid = (S/128, NH, B).
// ---------------------------------------------------------------------------
__global__ __launch_bounds__(128, 2) void mqa_attn_tc9(
    const unsigned* __restrict__ qp, const unsigned* __restrict__ kp,
    const unsigned* __restrict__ vp, unsigned* __restrict__ outp)
{
    extern __shared__ unsigned sm[];
    unsigned* Ks = sm;                    // [2][64][72]
    unsigned* Vs = sm + 2 * 64 * 72;      // [2][4096]

    const int b = blockIdx.z, h = blockIdx.y;
    const int qBase = blockIdx.x * 128;
    const int tid = threadIdx.x, wid = tid >> 5, lane = tid & 31;
    const int g = lane >> 2, tg = lane & 3;

    unsigned qa[2][8][4];
#pragma unroll
    for (int mi = 0; mi < 2; mi++) {
        int row = qBase + wid * 32 + mi * 16 + g;
        const unsigned* q0 = qp + (size_t)(b * SS + row) * HH + h * HDIM;
#pragma unroll
        for (int kf = 0; kf < 8; kf++) {
            int col = kf * 8 + tg;
            qa[mi][kf][0] = __ldg(q0 + col);
            qa[mi][kf][1] = __ldg(q0 + (size_t)8 * HH + col);
            qa[mi][kf][2] = __ldg(q0 + col + 4);
            qa[mi][kf][3] = __ldg(q0 + (size_t)8 * HH + col + 4);
        }
    }

    float o[2][8][4];
#pragma unroll
    for (int mi = 0; mi < 2; mi++)
#pragma unroll
        for (int nj = 0; nj < 8; nj++)
#pragma unroll
            for (int r = 0; r < 4; r++) o[mi][nj][r] = 0.0f;
    float lp[4] = {0.0f, 0.0f, 0.0f, 0.0f};

    auto issue = [&](int t, int buf) {
        const unsigned* kg = kp + (size_t)(b * SS + t * 64) * HDIM;
        unsigned* kb = Ks + buf * 64 * 72;
#pragma unroll
        for (int i = 0; i < 8; i++) {
            int ch = tid + i * 128;
            int r = ch >> 4, cw = ch & 15;
            cpa16(kb + r * 72 + cw * 4, kg + r * 64 + cw * 4);
        }
        const unsigned* vg = vp + (size_t)(b * SS + t * 64) * HDIM;
        unsigned* vb = Vs + buf * 4096;
#pragma unroll
        for (int i = 0; i < 8; i++) {
            int ch = tid + i * 128;
            cpa16(vb + ch * 4, vg + ch * 4);
        }
    };

    issue(0, 0);
    CP_COMMIT();

    const int T = SS / 64;
    for (int t = 0; t < T; t++) {
        CP_WAIT0();
        __syncthreads();
        if (t + 1 < T) {
            issue(t + 1, (t + 1) & 1);
            CP_COMMIT();
        }

        const unsigned* Kb = Ks + (t & 1) * 64 * 72;
        const unsigned* Vb = Vs + (t & 1) * 4096;

#pragma unroll
        for (int hf = 0; hf < 2; hf++) {
            float s[2][4][4];
#pragma unroll
            for (int mi = 0; mi < 2; mi++)
#pragma unroll
                for (int nj = 0; nj < 4; nj++)
#pragma unroll
                    for (int r = 0; r < 4; r++) s[mi][nj][r] = 0.0f;
#pragma unroll
            for (int kf = 0; kf < 8; kf++) {
#pragma unroll
                for (int nj = 0; nj < 4; nj++) {
                    uint2 bb = *(const uint2*)(Kb + (hf * 32 + nj * 8 + g) * 72 + kf * 8 + tg * 2);
                    mma_tf32(s[0][nj], qa[0][kf][0], qa[0][kf][1], qa[0][kf][2], qa[0][kf][3], bb.x, bb.y);
                    mma_tf32(s[1][nj], qa[1][kf][0], qa[1][kf][1], qa[1][kf][2], qa[1][kf][3], bb.x, bb.y);
                }
            }

            unsigned pa[2][4][4];
#pragma unroll
            for (int mi = 0; mi < 2; mi++)
#pragma unroll
                for (int nj = 0; nj < 4; nj++) {
                    float p0 = ex2(s[mi][nj][0]);
                    float p1 = ex2(s[mi][nj][1]);
                    float p2 = ex2(s[mi][nj][2]);
                    float p3 = ex2(s[mi][nj][3]);
                    lp[mi * 2 + 0] += p0 + p1;
                    lp[mi * 2 + 1] += p2 + p3;
                    pa[mi][nj][0] = f2tf(p0);
                    pa[mi][nj][1] = f2tf(p2);
                    pa[mi][nj][2] = f2tf(p1);
                    pa[mi][nj][3] = f2tf(p3);
                }

#pragma unroll
            for (int nj = 0; nj < 8; nj++) {
#pragma unroll
                for (int kf = 0; kf < 4; kf++) {
                    uint2 bb = *(const uint2*)(Vb + (hf * 4 + kf) * 512 + (nj * 8 + g) * 8 + tg * 2);
                    mma_tf32(o[0][nj], pa[0][kf][0], pa[0][kf][1], pa[0][kf][2], pa[0][kf][3], bb.x, bb.y);
                    mma_tf32(o[1][nj], pa[1][kf][0], pa[1][kf][1], pa[1][kf][2], pa[1][kf][3], bb.x, bb.y);
                }
            }
        }
    }

#pragma unroll
    for (int r = 0; r < 4; r++) {
        lp[r] += __shfl_xor_sync(0xffffffffu, lp[r], 1);
        lp[r] += __shfl_xor_sync(0xffffffffu, lp[r], 2);
        lp[r] = 1.0f / lp[r];
    }
#pragma unroll
    for (int mi = 0; mi < 2; mi++) {
        int row = qBase + wid * 32 + mi * 16 + g;
        size_t base = (size_t)(b * SS + row) * HH;
#pragma unroll
        for (int nj = 0; nj < 8; nj++) {
            int cg = h * HDIM + nj * 8 + 2 * tg;
            outp[base + perm8(cg)]                      = f2tf(o[mi][nj][0] * lp[mi * 2]);
            outp[base + perm8(cg + 1)]                  = f2tf(o[mi][nj][1] * lp[mi * 2]);
            outp[base + (size_t)8 * HH + perm8(cg)]     = f2tf(o[mi][nj][2] * lp[mi * 2 + 1]);
            outp[base + (size_t)8 * HH + perm8(cg + 1)] = f2tf(o[mi][nj][3] * lp[mi * 2 + 1]);
        }
    }
}

// ---------------------------------------------------------------------------
extern "C" void kernel_launch(void* const* d_in, const int* in_sizes, int n_in,
                              void* d_out, int out_size)
{
    const float* X  = (const float*)d_in[0];
    const float* Wq = (const float*)d_in[1];
    const float* bq = (const float*)d_in[2];
    const float* Wk = (const float*)d_in[3];
    const float* bk = (const float*)d_in[4];
    const float* Wv = (const float*)d_in[5];
    const float* bv = (const float*)d_in[6];
    const float* Wo = (const float*)d_in[7];
    const float* bo = (const float*)d_in[8];
    float* out = (float*)d_out;

    unsigned *xp, *wqkv, *wo, *q, *k, *v, *at;
    cudaGetSymbolAddress((void**)&xp,   g_xp);
    cudaGetSymbolAddress((void**)&wqkv, g_wqkv);
    cudaGetSymbolAddress((void**)&wo,   g_wo);
    cudaGetSymbolAddress((void**)&q,    g_q);
    cudaGetSymbolAddress((void**)&k,    g_k);
    cudaGetSymbolAddress((void**)&v,    g_v);
    cudaGetSymbolAddress((void**)&at,   g_at);

    const int smA  = (2 * 128 * 40 + 2 * 4 * 128 * 8) * 4;   // 73728 (2 CTAs/SM)
    const int smAt = (2 * 64 * 72 + 2 * 4096) * 4;           // 69632

    cudaFuncSetAttribute(gemm_db<0>, cudaFuncAttributeMaxDynamicSharedMemorySize, smA);
    cudaFuncSetAttribute(gemm_db<5>, cudaFuncAttributeMaxDynamicSharedMemorySize, smA);
    cudaFuncSetAttribute(gemm_db<0>, cudaFuncAttributePreferredSharedMemoryCarveout, 100);
    cudaFuncSetAttribute(gemm_db<5>, cudaFuncAttributePreferredSharedMemoryCarveout, 100);
    cudaFuncSetAttribute(mqa_attn_tc9, cudaFuncAttributeMaxDynamicSharedMemorySize, smAt);
    cudaFuncSetAttribute(mqa_attn_tc9, cudaFuncAttributePreferredSharedMemoryCarveout, 100);

    const float qscale = 0.125f * 1.44269504088896340736f;  // 1/sqrt(64) * log2(e)

    // launch 1: all converts fused (X + weights)
    const int ncvt = NX4 + NW;
    cvt_fused<<<(ncvt + 255) / 256, 256>>>(
        (const float4*)X, Wq, Wk, Wv, Wo, (uint4*)xp, wqkv, wo);
    // launch 2: fused QKV projection
    gemm_db<5><<<dim3(NQKV / 128, MM / 128), 128, smA>>>(
        xp, wqkv, bq, bk, bv, q, k, v, MM, NQKV, HH, qscale);
    // launch 3: attention
    mqa_attn_tc9<<<dim3(SS / 128, NHEAD, BB), 128, smAt>>>(q, k, v, at);
    // launch 4: output projection
    gemm_db<0><<<dim3(HH / 128, MM / 128), 128, smA>>>(
        at, wo, bo, nullptr, nullptr, out, nullptr, nullptr, MM, HH, HH, 1.0f);
}

// round 17
// speedup vs baseline: 1.8681x; 1.0294x over previous
#include <cuda_runtime.h>
#include <math.h>

#define BB 4
#define SS 2048
#define HH 1024
#define NHEAD 16
#define HDIM 64
#define MM (BB * SS)   // 8192
#define NQKV 1152      // 1024 (Q) + 64 (K) + 64 (V)

// ---------------------------------------------------------------------------
// scratch (__device__ globals; allocation-free)
// ---------------------------------------------------------------------------
__device__ unsigned g_xp[MM * HH];         // X, tf32, pair-interleaved cols
__device__ unsigned g_wqkv[HH * NQKV];     // Wq|Wk|Wv packed, kperm layout
__device__ unsigned g_wo[HH * HH];         // Wo, kperm layout
__device__ unsigned g_q [MM * HH];         // Q, tf32, pre-scaled 0.125*log2e (plain)
__device__ unsigned g_k [MM * HDIM];       // K, tf32, pair-interleaved cols
__device__ unsigned g_v [MM * HDIM];       // V, tf32, natural [s/8][d][8]
__device__ unsigned g_at[MM * HH];         // attn out, tf32, pair-interleaved

// ---------------------------------------------------------------------------
// helpers
// ---------------------------------------------------------------------------
__device__ __forceinline__ unsigned f2tf(float f) {
    unsigned u;
    asm("cvt.rna.tf32.f32 %0, %1;" : "=r"(u) : "f"(f));
    return u;
}
__device__ __forceinline__ float ex2(float f) {
    float r;
    asm("ex2.approx.f32 %0, %1;" : "=f"(r) : "f"(f));
    return r;
}
__device__ __forceinline__ int perm8(int c) {
    return (c & ~7) | ((c & 3) << 1) | ((c >> 2) & 1);
}
__device__ __forceinline__ size_t kperm(int k, int n, int N) {
    return (size_t)(k >> 3) * N * 8 + n * 8 + (k & 3) * 2 + ((k >> 2) & 1);
}
// natural V layout: key s, dim d -> word (s/8)*512 + d*8 + (s%8)
__device__ __forceinline__ size_t vnat(int s, int d) {
    return (size_t)(s >> 3) * (HDIM * 8) + d * 8 + (s & 7);
}
__device__ __forceinline__ void mma_tf32(float c[4],
                                         unsigned a0, unsigned a1,
                                         unsigned a2, unsigned a3,
                                         unsigned b0, unsigned b1) {
    asm volatile(
        "mma.sync.aligned.m16n8k8.row.col.f32.tf32.tf32.f32 "
        "{%0,%1,%2,%3}, {%4,%5,%6,%7}, {%8,%9}, {%0,%1,%2,%3};"
        : "+f"(c[0]), "+f"(c[1]), "+f"(c[2]), "+f"(c[3])
        : "r"(a0), "r"(a1), "r"(a2), "r"(a3), "r"(b0), "r"(b1));
}
__device__ __forceinline__ void cpa16(unsigned* smem_dst, const unsigned* gmem_src) {
    unsigned s = (unsigned)__cvta_generic_to_shared(smem_dst);
    asm volatile("cp.async.cg.shared.global [%0], [%1], 16;" :: "r"(s), "l"(gmem_src));
}
#define CP_COMMIT() asm volatile("cp.async.commit_group;")
#define CP_WAIT0()  asm volatile("cp.async.wait_group 0;")

// ---------------------------------------------------------------------------
// single fused pre-convert kernel (round-16 winner, unchanged)
// ---------------------------------------------------------------------------
#define NX4 (MM * HH / 4)
#define NW  (2 * HH * HH + HH * 128)
__global__ void cvt_fused(const float4* __restrict__ X4,
                          const float* __restrict__ Wq, const float* __restrict__ Wk,
                          const float* __restrict__ Wv, const float* __restrict__ Wo_,
                          uint4* __restrict__ xp4, unsigned* __restrict__ wqkv,
                          unsigned* __restrict__ wo)
{
    int idx = blockIdx.x * 256 + threadIdx.x;
    if (idx < NX4) {
        float4 v = X4[idx];
        unsigned x0 = f2tf(v.x), x1 = f2tf(v.y), x2 = f2tf(v.z), x3 = f2tf(v.w);
        bool odd = threadIdx.x & 1;
        unsigned a = odd ? x0 : x2;
        unsigned b = odd ? x1 : x3;
        unsigned sa = __shfl_xor_sync(0xffffffffu, a, 1);
        unsigned sb = __shfl_xor_sync(0xffffffffu, b, 1);
        uint4 o;
        if (!odd) { o.x = x0; o.y = sa; o.z = x1; o.w = sb; }
        else      { o.x = sa; o.y = x2; o.z = sb; o.w = x3; }
        xp4[idx] = o;
    } else {
        int i = idx - NX4;
        if (i < HH * HH) {
            int nn = i & (HH - 1), k = i >> 10;
            wqkv[kperm(k, nn, NQKV)] = f2tf(Wq[i]);
        } else if (i < HH * HH + HH * 128) {
            int j = i - HH * HH;
            int nn = j & 127, k = j >> 7;
            float v = (nn < HDIM) ? Wk[k * HDIM + nn] : Wv[k * HDIM + nn - HDIM];
            wqkv[kperm(k, HH + nn, NQKV)] = f2tf(v);
        } else if (i < NW) {
            int j = i - HH * HH - HH * 128;
            int nn = j & (HH - 1), k = j >> 10;
            wo[kperm(k, nn, HH)] = f2tf(Wo_[j]);
        }
    }
}

// ---------------------------------------------------------------------------
// double-buffered tf32 GEMM v5: BM=64 -> acc 64 regs -> 3 CTAs/SM (12 warps).
// A: pair-interleaved cols [M][K]. W: kperm [K/8][N][8].
// BM=64, BN=128, BK=32, 4 warps (2m x 2n), warp tile 32x64.
// MODE 0: fp32+bias -> final out. MODE 5: QKV routing epilogue.
// Per-output k-summation order identical to previous GEMMs.
// ---------------------------------------------------------------------------
template <int MODE>
__global__ __launch_bounds__(128, 3) void gemm_db(
    const unsigned* __restrict__ A, const unsigned* __restrict__ W,
    const float* __restrict__ bias, const float* __restrict__ bias2,
    const float* __restrict__ bias3,
    void* __restrict__ Cout, void* __restrict__ Cout2, void* __restrict__ Cout3,
    int M, int N, int K, float oscale)
{
    constexpr int BM = 64, BN = 128, BK = 32;
    constexpr int NTHR = 128;
    constexpr int AST = 40;
    constexpr int BWORDS = 4 * BN * 8;     // 4096 words

    extern __shared__ unsigned sm[];
    unsigned* As = sm;                     // [2][BM][AST]  (64*40 = 2560 words/buf)
    unsigned* Bs = sm + 2 * BM * AST;      // [2][4][BN*8]

    const int tid = threadIdx.x;
    const int wid = tid >> 5, lane = tid & 31, g = lane >> 2, tg = lane & 3;
    const int wm = (wid & 1) * 32;
    const int wn = (wid >> 1) * 64;
    const int rowBase = blockIdx.y * BM, colBase = blockIdx.x * BN;

    float acc[2][8][4];
#pragma unroll
    for (int mi = 0; mi < 2; mi++)
#pragma unroll
        for (int nj = 0; nj < 8; nj++)
#pragma unroll
            for (int r = 0; r < 4; r++) acc[mi][nj][r] = 0.0f;

    auto issue = [&](int kt, int buf) {
        const unsigned* Ag = A + (size_t)rowBase * K + kt;
        unsigned* Ab = As + buf * BM * AST;
#pragma unroll
        for (int i = 0; i < (BM * BK / 4) / NTHR; i++) {   // 4 chunks
            int ch = tid + i * NTHR;
            int r = ch >> 3, cw = ch & 7;
            cpa16(Ab + r * AST + cw * 4, Ag + (size_t)r * K + cw * 4);
        }
        const unsigned* Wg = W + (size_t)(kt >> 3) * N * 8 + (size_t)colBase * 8;
        unsigned* Bb = Bs + buf * BWORDS;
#pragma unroll
        for (int i = 0; i < (BWORDS / 4) / NTHR; i++) {    // 8 chunks
            int ch = tid + i * NTHR;
            int r = ch >> 8, cw = ch & 255;
            cpa16(Bb + r * BN * 8 + cw * 4, Wg + (size_t)r * N * 8 + cw * 4);
        }
    };

    issue(0, 0);
    CP_COMMIT();

    const int T = K / BK;
    for (int t = 0; t < T; t++) {
        CP_WAIT0();
        __syncthreads();
        if (t + 1 < T) {
            issue((t + 1) * BK, (t + 1) & 1);
            CP_COMMIT();
        }

        const unsigned* Ab = As + (t & 1) * BM * AST;
        const unsigned* Bb = Bs + (t & 1) * BWORDS;
#pragma unroll
        for (int ks = 0; ks < 4; ks++) {
            unsigned a[2][4];
#pragma unroll
            for (int mi = 0; mi < 2; mi++) {
                int row = wm + mi * 16 + g;
                uint2 lo = *(const uint2*)(Ab + row * AST + ks * 8 + tg * 2);
                uint2 hi = *(const uint2*)(Ab + (row + 8) * AST + ks * 8 + tg * 2);
                a[mi][0] = lo.x; a[mi][2] = lo.y;
                a[mi][1] = hi.x; a[mi][3] = hi.y;
            }
#pragma unroll
            for (int nj = 0; nj < 8; nj++) {
                uint2 bb = *(const uint2*)(Bb + ks * BN * 8 + (wn + nj * 8 + g) * 8 + tg * 2);
#pragma unroll
                for (int mi = 0; mi < 2; mi++)
                    mma_tf32(acc[mi][nj], a[mi][0], a[mi][1], a[mi][2], a[mi][3], bb.x, bb.y);
            }
        }
    }

    // epilogue
#pragma unroll
    for (int nj = 0; nj < 8; nj++) {
        int col = colBase + wn + nj * 8 + 2 * tg;
        float bx, by;
        if (MODE == 5) {
            if (col < HH)            { bx = bias[col];        by = bias[col + 1]; }
            else if (col < HH + 64)  { bx = bias2[col - HH];  by = bias2[col - HH + 1]; }
            else                     { bx = bias3[col - HH - 64]; by = bias3[col - HH - 63]; }
        } else {
            bx = bias[col]; by = bias[col + 1];
        }
#pragma unroll
        for (int mi = 0; mi < 2; mi++) {
            int row = rowBase + wm + mi * 16 + g;
            float v00 = acc[mi][nj][0] + bx, v01 = acc[mi][nj][1] + by;
            float v10 = acc[mi][nj][2] + bx, v11 = acc[mi][nj][3] + by;
            if (MODE == 0) {
                float* o = (float*)Cout;
                *(float2*)(o + (size_t)row * N + col) = make_float2(v00, v01);
                *(float2*)(o + (size_t)(row + 8) * N + col) = make_float2(v10, v11);
            } else {
                if (col < HH) {
                    unsigned* o = (unsigned*)Cout;
                    *(uint2*)(o + (size_t)row * HH + col) =
                        make_uint2(f2tf(v00 * oscale), f2tf(v01 * oscale));
                    *(uint2*)(o + (size_t)(row + 8) * HH + col) =
                        make_uint2(f2tf(v10 * oscale), f2tf(v11 * oscale));
                } else if (col < HH + 64) {
                    unsigned* o = (unsigned*)Cout2;
                    int d = col - HH;
                    o[(size_t)row * HDIM + perm8(d)]           = f2tf(v00);
                    o[(size_t)row * HDIM + perm8(d + 1)]       = f2tf(v01);
                    o[(size_t)(row + 8) * HDIM + perm8(d)]     = f2tf(v10);
                    o[(size_t)(row + 8) * HDIM + perm8(d + 1)] = f2tf(v11);
                } else {
                    unsigned* o = (unsigned*)Cout3;
                    int d = col - HH - 64;
                    o[vnat(row, d)]         = f2tf(v00);
                    o[vnat(row, d + 1)]     = f2tf(v01);
                    o[vnat(row + 8, d)]     = f2tf(v10);
                    o[vnat(row + 8, d + 1)] = f2tf(v11);
                }
            }
        }
    }
}

// ---------------------------------------------------------------------------
// MQA flash attention v9 (round-12..16 winner, unchanged): 128-thread CTAs,
// 2 m-frags/warp, Q register-resident, S C-frag -> PV A-frag direct,
// V natural key order, no online max. grid = (S/128, NH, B).
// ---------------------------------------------------------------------------
__global__ __launch_bounds__(128, 2) void mqa_attn_tc9(
    const unsigned* __restrict__ qp, const unsigned* __restrict__ kp,
    const unsigned* __restrict__ vp, unsigned* __restrict__ outp)
{
    extern __shared__ unsigned sm[];
    unsigned* Ks = sm;                    // [2][64][72]
    unsigned* Vs = sm + 2 * 64 * 72;      // [2][4096]

    const int b = blockIdx.z, h = blockIdx.y;
    const int qBase = blockIdx.x * 128;
    const int tid = threadIdx.x, wid = tid >> 5, lane = tid & 31;
    const int g = lane >> 2, tg = lane & 3;

    unsigned qa[2][8][4];
#pragma unroll
    for (int mi = 0; mi < 2; mi++) {
        int row = qBase + wid * 32 + mi * 16 + g;
        const unsigned* q0 = qp + (size_t)(b * SS + row) * HH + h * HDIM;
#pragma unroll
        for (int kf = 0; kf < 8; kf++) {
            int col = kf * 8 + tg;
            qa[mi][kf][0] = __ldg(q0 + col);
            qa[mi][kf][1] = __ldg(q0 + (size_t)8 * HH + col);
            qa[mi][kf][2] = __ldg(q0 + col + 4);
            qa[mi][kf][3] = __ldg(q0 + (size_t)8 * HH + col + 4);
        }
    }

    float o[2][8][4];
#pragma unroll
    for (int mi = 0; mi < 2; mi++)
#pragma unroll
        for (int nj = 0; nj < 8; nj++)
#pragma unroll
            for (int r = 0; r < 4; r++) o[mi][nj][r] = 0.0f;
    float lp[4] = {0.0f, 0.0f, 0.0f, 0.0f};

    auto issue = [&](int t, int buf) {
        const unsigned* kg = kp + (size_t)(b * SS + t * 64) * HDIM;
        unsigned* kb = Ks + buf * 64 * 72;
#pragma unroll
        for (int i = 0; i < 8; i++) {
            int ch = tid + i * 128;
            int r = ch >> 4, cw = ch & 15;
            cpa16(kb + r * 72 + cw * 4, kg + r * 64 + cw * 4);
        }
        const unsigned* vg = vp + (size_t)(b * SS + t * 64) * HDIM;
        unsigned* vb = Vs + buf * 4096;
#pragma unroll
        for (int i = 0; i < 8; i++) {
            int ch = tid + i * 128;
            cpa16(vb + ch * 4, vg + ch * 4);
        }
    };

    issue(0, 0);
    CP_COMMIT();

    const int T = SS / 64;
    for (int t = 0; t < T; t++) {
        CP_WAIT0();
        __syncthreads();
        if (t + 1 < T) {
            issue(t + 1, (t + 1) & 1);
            CP_COMMIT();
        }

        const unsigned* Kb = Ks + (t & 1) * 64 * 72;
        const unsigned* Vb = Vs + (t & 1) * 4096;

#pragma unroll
        for (int hf = 0; hf < 2; hf++) {
            float s[2][4][4];
#pragma unroll
            for (int mi = 0; mi < 2; mi++)
#pragma unroll
                for (int nj = 0; nj < 4; nj++)
#pragma unroll
                    for (int r = 0; r < 4; r++) s[mi][nj][r] = 0.0f;
#pragma unroll
            for (int kf = 0; kf < 8; kf++) {
#pragma unroll
                for (int nj = 0; nj < 4; nj++) {
                    uint2 bb = *(const uint2*)(Kb + (hf * 32 + nj * 8 + g) * 72 + kf * 8 + tg * 2);
                    mma_tf32(s[0][nj], qa[0][kf][0], qa[0][kf][1], qa[0][kf][2], qa[0][kf][3], bb.x, bb.y);
                    mma_tf32(s[1][nj], qa[1][kf][0], qa[1][kf][1], qa[1][kf][2], qa[1][kf][3], bb.x, bb.y);
                }
            }

            unsigned pa[2][4][4];
#pragma unroll
            for (int mi = 0; mi < 2; mi++)
#pragma unroll
                for (int nj = 0; nj < 4; nj++) {
                    float p0 = ex2(s[mi][nj][0]);
                    float p1 = ex2(s[mi][nj][1]);
                    float p2 = ex2(s[mi][nj][2]);
                    float p3 = ex2(s[mi][nj][3]);
                    lp[mi * 2 + 0] += p0 + p1;
                    lp[mi * 2 + 1] += p2 + p3;
                    pa[mi][nj][0] = f2tf(p0);
                    pa[mi][nj][1] = f2tf(p2);
                    pa[mi][nj][2] = f2tf(p1);
                    pa[mi][nj][3] = f2tf(p3);
                }

#pragma unroll
            for (int nj = 0; nj < 8; nj++) {
#pragma unroll
                for (int kf = 0; kf < 4; kf++) {
                    uint2 bb = *(const uint2*)(Vb + (hf * 4 + kf) * 512 + (nj * 8 + g) * 8 + tg * 2);
                    mma_tf32(o[0][nj], pa[0][kf][0], pa[0][kf][1], pa[0][kf][2], pa[0][kf][3], bb.x, bb.y);
                    mma_tf32(o[1][nj], pa[1][kf][0], pa[1][kf][1], pa[1][kf][2], pa[1][kf][3], bb.x, bb.y);
                }
            }
        }
    }

#pragma unroll
    for (int r = 0; r < 4; r++) {
        lp[r] += __shfl_xor_sync(0xffffffffu, lp[r], 1);
        lp[r] += __shfl_xor_sync(0xffffffffu, lp[r], 2);
        lp[r] = 1.0f / lp[r];
    }
#pragma unroll
    for (int mi = 0; mi < 2; mi++) {
        int row = qBase + wid * 32 + mi * 16 + g;
        size_t base = (size_t)(b * SS + row) * HH;
#pragma unroll
        for (int nj = 0; nj < 8; nj++) {
            int cg = h * HDIM + nj * 8 + 2 * tg;
            outp[base + perm8(cg)]                      = f2tf(o[mi][nj][0] * lp[mi * 2]);
            outp[base + perm8(cg + 1)]                  = f2tf(o[mi][nj][1] * lp[mi * 2]);
            outp[base + (size_t)8 * HH + perm8(cg)]     = f2tf(o[mi][nj][2] * lp[mi * 2 + 1]);
            outp[base + (size_t)8 * HH + perm8(cg + 1)] = f2tf(o[mi][nj][3] * lp[mi * 2 + 1]);
        }
    }
}

// ---------------------------------------------------------------------------
extern "C" void kernel_launch(void* const* d_in, const int* in_sizes, int n_in,
                              void* d_out, int out_size)
{
    const float* X  = (const float*)d_in[0];
    const float* Wq = (const float*)d_in[1];
    const float* bq = (const float*)d_in[2];
    const float* Wk = (const float*)d_in[3];
    const float* bk = (const float*)d_in[4];
    const float* Wv = (const float*)d_in[5];
    const float* bv = (const float*)d_in[6];
    const float* Wo = (const float*)d_in[7];
    const float* bo = (const float*)d_in[8];
    float* out = (float*)d_out;

    unsigned *xp, *wqkv, *wo, *q, *k, *v, *at;
    cudaGetSymbolAddress((void**)&xp,   g_xp);
    cudaGetSymbolAddress((void**)&wqkv, g_wqkv);
    cudaGetSymbolAddress((void**)&wo,   g_wo);
    cudaGetSymbolAddress((void**)&q,    g_q);
    cudaGetSymbolAddress((void**)&k,    g_k);
    cudaGetSymbolAddress((void**)&v,    g_v);
    cudaGetSymbolAddress((void**)&at,   g_at);

    const int smA  = (2 * 64 * 40 + 2 * 4 * 128 * 8) * 4;    // 53248 (3 CTAs/SM)
    const int smAt = (2 * 64 * 72 + 2 * 4096) * 4;           // 69632

    cudaFuncSetAttribute(gemm_db<0>, cudaFuncAttributeMaxDynamicSharedMemorySize, smA);
    cudaFuncSetAttribute(gemm_db<5>, cudaFuncAttributeMaxDynamicSharedMemorySize, smA);
    cudaFuncSetAttribute(gemm_db<0>, cudaFuncAttributePreferredSharedMemoryCarveout, 100);
    cudaFuncSetAttribute(gemm_db<5>, cudaFuncAttributePreferredSharedMemoryCarveout, 100);
    cudaFuncSetAttribute(mqa_attn_tc9, cudaFuncAttributeMaxDynamicSharedMemorySize, smAt);
    cudaFuncSetAttribute(mqa_attn_tc9, cudaFuncAttributePreferredSharedMemoryCarveout, 100);

    const float qscale = 0.125f * 1.44269504088896340736f;  // 1/sqrt(64) * log2(e)

    // launch 1: all converts fused (X + weights)
    const int ncvt = NX4 + NW;
    cvt_fused<<<(ncvt + 255) / 256, 256>>>(
        (const float4*)X, Wq, Wk, Wv, Wo, (uint4*)xp, wqkv, wo);
    // launch 2: fused QKV projection (BM=64, 3 CTAs/SM)
    gemm_db<5><<<dim3(NQKV / 128, MM / 64), 128, smA>>>(
        xp, wqkv, bq, bk, bv, q, k, v, MM, NQKV, HH, qscale);
    // launch 3: attention
    mqa_attn_tc9<<<dim3(SS / 128, NHEAD, BB), 128, smAt>>>(q, k, v, at);
    // launch 4: output projection
    gemm_db<0><<<dim3(HH / 128, MM / 64), 128, smA>>>(
        at, wo, bo, nullptr, nullptr, out, nullptr, nullptr, MM, HH, HH, 1.0f);
}